// round 2
// baseline (speedup 1.0000x reference)
#include <cuda_runtime.h>

#define NN 50000
#define EE 800000
#define GG 512
#define NFD 32
#define EFD 16

// ---------------- scratch (no allocations allowed) ----------------
__device__ float g_bufA[NN * 256];
__device__ float g_bufB[NN * 256];
__device__ float g_agg[NN * 256];
__device__ float g_deg[NN];
__device__ float g_gcnt[GG];

// packed f32x2 FMA (sm_103a): d = a*b + c on both 32-bit halves
#define FMA2(d, a, b, c) \
    asm("fma.rn.f32x2 %0, %1, %2, %3;" : "=l"(d) : "l"(a), "l"(b), "l"(c))

__global__ void count_kernel(const int* __restrict__ dst, const int* __restrict__ gid,
                             float* __restrict__ deg, float* __restrict__ gcnt) {
    int i = blockIdx.x * blockDim.x + threadIdx.x;
    if (i < EE) atomicAdd(&deg[dst[i]], 1.0f);
    if (i < NN) atomicAdd(&gcnt[gid[i]], 1.0f);
}

// ---------------- edge kernel: m = relu([x[src], e] @ Wm + bm); atomic scatter to agg[dst]
// warp handles 4 edges; lane owns columns {p*64 + 2*lane, +1} for p in [0, F/64)
template <int FIN, int F>
__global__ __launch_bounds__(256) void edge_kernel(
    const float* __restrict__ xin, const float* __restrict__ efeat,
    const int* __restrict__ src, const int* __restrict__ dst,
    const float* __restrict__ Wm, const float* __restrict__ bm,
    float* __restrict__ agg)
{
    constexpr int K = FIN + EFD;
    constexpr int P = F / 64;
    extern __shared__ float smem[];
    float* Wm_s = smem;                 // K*F
    float* in_s = smem + K * F;         // 32*K
    int*   sdst = (int*)(in_s + 32 * K);
    int*   ssrc = sdst + 32;

    const int tid = threadIdx.x;
    const int w = tid >> 5, lane = tid & 31;

    for (int i = tid; i < K * F; i += 256) Wm_s[i] = Wm[i];
    float bmr[P][2];
    #pragma unroll
    for (int p = 0; p < P; p++) {
        bmr[p][0] = bm[p * 64 + lane * 2];
        bmr[p][1] = bm[p * 64 + lane * 2 + 1];
    }
    __syncthreads();

    const int nTiles = EE / 32;  // 25000, exact
    for (int tile = blockIdx.x; tile < nTiles; tile += gridDim.x) {
        const int base = tile * 32;
        __syncthreads();  // protect in_s reuse across tiles
        if (tid < 32) { ssrc[tid] = src[base + tid]; sdst[tid] = dst[base + tid]; }
        __syncthreads();

        // gather: 32 rows of K floats (float4 granularity; FIN % 4 == 0)
        for (int i = tid; i < 32 * (K / 4); i += 256) {
            int el = i / (K / 4);
            int k4 = (i % (K / 4)) * 4;
            float4 v;
            if (k4 < FIN) v = *(const float4*)&xin[(size_t)ssrc[el] * FIN + k4];
            else          v = *(const float4*)&efeat[(size_t)(base + el) * EFD + (k4 - FIN)];
            *(float4*)&in_s[el * K + k4] = v;
        }
        __syncthreads();

        unsigned long long acc[4][P];
        #pragma unroll
        for (int e = 0; e < 4; e++)
            #pragma unroll
            for (int p = 0; p < P; p++) acc[e][p] = 0ull;

        const unsigned long long* Wm2 = (const unsigned long long*)Wm_s;
        const float* in0 = &in_s[(w * 4) * K];

        #pragma unroll 4
        for (int k = 0; k < K; k++) {
            unsigned long long vv[4];
            #pragma unroll
            for (int e = 0; e < 4; e++) {
                float v = in0[e * K + k];  // LDS broadcast
                asm("mov.b64 %0, {%1, %1};" : "=l"(vv[e]) : "r"(__float_as_uint(v)));
            }
            #pragma unroll
            for (int p = 0; p < P; p++) {
                unsigned long long w2 = Wm2[k * (F / 2) + p * 32 + lane];
                #pragma unroll
                for (int e = 0; e < 4; e++) FMA2(acc[e][p], vv[e], w2, acc[e][p]);
            }
        }

        // epilogue: bias + relu + atomic scatter-add (skip zeros: halves atomic traffic)
        #pragma unroll
        for (int e = 0; e < 4; e++) {
            int d = sdst[w * 4 + e];
            float* aggrow = agg + (size_t)d * F;
            #pragma unroll
            for (int p = 0; p < P; p++) {
                float lo = __uint_as_float((unsigned)acc[e][p]) + bmr[p][0];
                float hi = __uint_as_float((unsigned)(acc[e][p] >> 32)) + bmr[p][1];
                if (lo > 0.0f) atomicAdd(&aggrow[p * 64 + lane * 2], lo);
                if (hi > 0.0f) atomicAdd(&aggrow[p * 64 + lane * 2 + 1], hi);
            }
        }
    }
}

// ---------------- node kernel: feat = relu(agg/deg + x @ Ws + bs); score += segmean(feat@Wc+bc)
template <int FIN, int F>
__global__ __launch_bounds__(256) void node_kernel(
    const float* __restrict__ xin, const float* __restrict__ agg,
    const float* __restrict__ Ws, const float* __restrict__ bs,
    const float* __restrict__ Wc, const float* __restrict__ bc,
    const int* __restrict__ gid, const float* __restrict__ deg,
    const float* __restrict__ gcnt,
    float* __restrict__ fout, float* __restrict__ score)
{
    constexpr int P = F / 64;
    extern __shared__ float smem[];
    float* Ws_s = smem;                  // FIN*F
    float* Wc_s = Ws_s + FIN * F;        // F
    float* in_s = Wc_s + F;              // 32*FIN

    const int tid = threadIdx.x;
    const int w = tid >> 5, lane = tid & 31;

    for (int i = tid; i < FIN * F; i += 256) Ws_s[i] = Ws[i];
    for (int i = tid; i < F; i += 256) Wc_s[i] = Wc[i];
    float bsr[P][2];
    #pragma unroll
    for (int p = 0; p < P; p++) {
        bsr[p][0] = bs[p * 64 + lane * 2];
        bsr[p][1] = bs[p * 64 + lane * 2 + 1];
    }
    const float bcv = bc[0];
    __syncthreads();

    const int nTiles = (NN + 31) / 32;
    for (int tile = blockIdx.x; tile < nTiles; tile += gridDim.x) {
        const int base = tile * 32;
        __syncthreads();
        for (int i = tid; i < 32 * (FIN / 4); i += 256) {
            int nl = i / (FIN / 4);
            int k4 = (i % (FIN / 4)) * 4;
            int n = base + nl;
            float4 v = make_float4(0.f, 0.f, 0.f, 0.f);
            if (n < NN) v = *(const float4*)&xin[(size_t)n * FIN + k4];
            *(float4*)&in_s[nl * FIN + k4] = v;
        }
        __syncthreads();

        unsigned long long acc[4][P];
        #pragma unroll
        for (int e = 0; e < 4; e++)
            #pragma unroll
            for (int p = 0; p < P; p++) acc[e][p] = 0ull;

        const unsigned long long* Ws2 = (const unsigned long long*)Ws_s;
        const float* in0 = &in_s[(w * 4) * FIN];

        #pragma unroll 4
        for (int k = 0; k < FIN; k++) {
            unsigned long long vv[4];
            #pragma unroll
            for (int e = 0; e < 4; e++) {
                float v = in0[e * FIN + k];
                asm("mov.b64 %0, {%1, %1};" : "=l"(vv[e]) : "r"(__float_as_uint(v)));
            }
            #pragma unroll
            for (int p = 0; p < P; p++) {
                unsigned long long w2 = Ws2[k * (F / 2) + p * 32 + lane];
                #pragma unroll
                for (int e = 0; e < 4; e++) FMA2(acc[e][p], vv[e], w2, acc[e][p]);
            }
        }

        #pragma unroll
        for (int e = 0; e < 4; e++) {
            int n = base + w * 4 + e;
            if (n >= NN) continue;
            float inv = 1.0f / fmaxf(deg[n], 1.0f);
            const float* arow = agg + (size_t)n * F;
            float* frow = fout + (size_t)n * F;
            float cpart = 0.0f;
            #pragma unroll
            for (int p = 0; p < P; p++) {
                int c0 = p * 64 + lane * 2;
                float2 av = *(const float2*)&arow[c0];
                float lo = fmaxf(av.x * inv + __uint_as_float((unsigned)acc[e][p]) + bsr[p][0], 0.0f);
                float hi = fmaxf(av.y * inv + __uint_as_float((unsigned)(acc[e][p] >> 32)) + bsr[p][1], 0.0f);
                float2 ov; ov.x = lo; ov.y = hi;
                *(float2*)&frow[c0] = ov;
                cpart += lo * Wc_s[c0] + hi * Wc_s[c0 + 1];
            }
            #pragma unroll
            for (int off = 16; off; off >>= 1)
                cpart += __shfl_xor_sync(0xFFFFFFFFu, cpart, off);
            if (lane == 0) {
                int g = gid[n];
                atomicAdd(&score[g], (cpart + bcv) / fmaxf(gcnt[g], 1.0f));
            }
        }
    }
}

// ---------------- host side ----------------
template <typename Kern>
static int grid_for(Kern k, int smem_bytes, int tiles, int nsm) {
    cudaFuncSetAttribute(k, cudaFuncAttributeMaxDynamicSharedMemorySize, smem_bytes);
    int occ = 1;
    cudaOccupancyMaxActiveBlocksPerMultiprocessor(&occ, k, 256, smem_bytes);
    if (occ < 1) occ = 1;
    int g = nsm * occ;
    if (g > tiles) g = tiles;
    return g;
}

template <int FIN, int F>
static void run_layer(const float* xin, const float* efeat, const int* src, const int* dst,
                      const int* gid, const float* const* Wl,
                      float* agg, float* fout, float* score,
                      float* deg, float* gcnt, int nsm)
{
    constexpr int K = FIN + EFD;
    const int smem_e = (K * F + 32 * K) * 4 + 64 * 4;
    const int smem_n = (FIN * F + F + 32 * FIN) * 4;

    cudaMemsetAsync(agg, 0, (size_t)NN * F * sizeof(float));
    int ge = grid_for(edge_kernel<FIN, F>, smem_e, EE / 32, nsm);
    edge_kernel<FIN, F><<<ge, 256, smem_e>>>(xin, efeat, src, dst, Wl[0], Wl[1], agg);
    int gn = grid_for(node_kernel<FIN, F>, smem_n, (NN + 31) / 32, nsm);
    node_kernel<FIN, F><<<gn, 256, smem_n>>>(xin, agg, Wl[2], Wl[3], Wl[4], Wl[5],
                                             gid, deg, gcnt, fout, score);
}

extern "C" void kernel_launch(void* const* d_in, const int* in_sizes, int n_in,
                              void* d_out, int out_size)
{
    const float* x   = (const float*)d_in[0];
    const float* e   = (const float*)d_in[1];
    const int*   src = (const int*)d_in[2];
    const int*   dst = (const int*)d_in[3];
    const int*   gid = (const int*)d_in[4];
    const float* W[4][6];
    for (int l = 0; l < 4; l++)
        for (int j = 0; j < 6; j++)
            W[l][j] = (const float*)d_in[5 + l * 6 + j];
    float* score = (float*)d_out;

    float *bufA, *bufB, *agg, *deg, *gcnt;
    cudaGetSymbolAddress((void**)&bufA, g_bufA);
    cudaGetSymbolAddress((void**)&bufB, g_bufB);
    cudaGetSymbolAddress((void**)&agg, g_agg);
    cudaGetSymbolAddress((void**)&deg, g_deg);
    cudaGetSymbolAddress((void**)&gcnt, g_gcnt);

    int nsm = 148;
    cudaDeviceGetAttribute(&nsm, cudaDevAttrMultiProcessorCount, 0);

    cudaMemsetAsync(deg, 0, NN * sizeof(float));
    cudaMemsetAsync(gcnt, 0, GG * sizeof(float));
    cudaMemsetAsync(score, 0, GG * sizeof(float));
    count_kernel<<<(EE + 255) / 256, 256>>>(dst, gid, deg, gcnt);

    run_layer<32, 64>  (x,    e, src, dst, gid, W[0], agg, bufA, score, deg, gcnt, nsm);
    run_layer<64, 128> (bufA, e, src, dst, gid, W[1], agg, bufB, score, deg, gcnt, nsm);
    run_layer<128, 128>(bufB, e, src, dst, gid, W[2], agg, bufA, score, deg, gcnt, nsm);
    run_layer<128, 256>(bufA, e, src, dst, gid, W[3], agg, bufB, score, deg, gcnt, nsm);
}

// round 3
// speedup vs baseline: 1.1308x; 1.1308x over previous
#include <cuda_runtime.h>

#define NN 50000
#define EE 800000
#define GG 512
#define NFD 32
#define EFD 16

// ---------------- scratch (no allocations allowed) ----------------
__device__ float g_bufA[NN * 256];
__device__ float g_bufB[NN * 256];
__device__ float g_agg[NN * 256];
__device__ float g_deg[NN];
__device__ float g_gcnt[GG];

// packed f32x2 FMA (sm_103a): d = a*b + c on both 32-bit halves
#define FMA2(d, a, b, c) \
    asm("fma.rn.f32x2 %0, %1, %2, %3;" : "=l"(d) : "l"(a), "l"(b), "l"(c))
#define DUP2(d, s) \
    asm("mov.b64 %0, {%1, %1};" : "=l"(d) : "r"(__float_as_uint(s)))

__global__ void count_kernel(const int* __restrict__ dst, const int* __restrict__ gid,
                             float* __restrict__ deg, float* __restrict__ gcnt) {
    int i = blockIdx.x * blockDim.x + threadIdx.x;
    if (i < EE) atomicAdd(&deg[dst[i]], 1.0f);
    if (i < NN) atomicAdd(&gcnt[gid[i]], 1.0f);
}

// ---------------- edge kernel: m = relu([x[src], e] @ Wm + bm); atomic scatter to agg[dst]
// Tile = 64 edges per block-iteration; warp w owns edges [w*8, w*8+8).
// Lane owns columns {p*64 + 2*lane, +1}, p in [0, F/64).
template <int FIN, int F>
__global__ __launch_bounds__(256) void edge_kernel(
    const float* __restrict__ xin, const float* __restrict__ efeat,
    const int* __restrict__ src, const int* __restrict__ dst,
    const float* __restrict__ Wm, const float* __restrict__ bm,
    float* __restrict__ agg)
{
    constexpr int K = FIN + EFD;
    constexpr int P = F / 64;
    constexpr int TILE = 64;
    constexpr int EPW = 8;
    extern __shared__ float smem[];
    float* Wm_s = smem;                   // K*F
    float* in_s = smem + K * F;           // TILE*K
    int*   sdst = (int*)(in_s + TILE * K);
    int*   ssrc = sdst + TILE;

    const int tid = threadIdx.x;
    const int w = tid >> 5, lane = tid & 31;

    for (int i = tid; i < K * F; i += 256) Wm_s[i] = Wm[i];
    float bmr[P][2];
    #pragma unroll
    for (int p = 0; p < P; p++) {
        bmr[p][0] = bm[p * 64 + lane * 2];
        bmr[p][1] = bm[p * 64 + lane * 2 + 1];
    }
    __syncthreads();

    const int nTiles = EE / TILE;  // 12500, exact
    for (int tile = blockIdx.x; tile < nTiles; tile += gridDim.x) {
        const int base = tile * TILE;
        __syncthreads();  // protect in_s reuse across tiles
        if (tid < TILE) { ssrc[tid] = src[base + tid]; sdst[tid] = dst[base + tid]; }
        __syncthreads();

        // gather: TILE rows of K floats (float4 granularity; FIN,EFD % 4 == 0)
        for (int i = tid; i < TILE * (K / 4); i += 256) {
            int el = i / (K / 4);
            int k4 = (i % (K / 4)) * 4;
            float4 v;
            if (k4 < FIN) v = *(const float4*)&xin[(size_t)ssrc[el] * FIN + k4];
            else          v = *(const float4*)&efeat[(size_t)(base + el) * EFD + (k4 - FIN)];
            *(float4*)&in_s[el * K + k4] = v;
        }
        __syncthreads();

        unsigned long long acc[EPW][P];
        #pragma unroll
        for (int e = 0; e < EPW; e++)
            #pragma unroll
            for (int p = 0; p < P; p++) acc[e][p] = 0ull;

        const unsigned long long* Wm2 = (const unsigned long long*)Wm_s;
        const float* in0 = &in_s[(w * EPW) * K];

        for (int k4 = 0; k4 < K; k4 += 4) {
            float4 vv[EPW];
            #pragma unroll
            for (int e = 0; e < EPW; e++)
                vv[e] = *(const float4*)&in0[e * K + k4];  // LDS.128 broadcast
            #pragma unroll
            for (int kk = 0; kk < 4; kk++) {
                const int k = k4 + kk;
                unsigned long long dup[EPW];
                #pragma unroll
                for (int e = 0; e < EPW; e++) {
                    float v = (kk == 0) ? vv[e].x : (kk == 1) ? vv[e].y
                             : (kk == 2) ? vv[e].z : vv[e].w;
                    DUP2(dup[e], v);
                }
                #pragma unroll
                for (int p = 0; p < P; p++) {
                    unsigned long long w2 = Wm2[k * (F / 2) + p * 32 + lane];
                    #pragma unroll
                    for (int e = 0; e < EPW; e++) FMA2(acc[e][p], dup[e], w2, acc[e][p]);
                }
            }
        }

        // epilogue: bias + relu + atomic scatter-add (skip zeros: halves atomic traffic)
        #pragma unroll
        for (int e = 0; e < EPW; e++) {
            int d = sdst[w * EPW + e];
            float* aggrow = agg + (size_t)d * F;
            #pragma unroll
            for (int p = 0; p < P; p++) {
                float lo = __uint_as_float((unsigned)acc[e][p]) + bmr[p][0];
                float hi = __uint_as_float((unsigned)(acc[e][p] >> 32)) + bmr[p][1];
                if (lo > 0.0f) atomicAdd(&aggrow[p * 64 + lane * 2], lo);
                if (hi > 0.0f) atomicAdd(&aggrow[p * 64 + lane * 2 + 1], hi);
            }
        }
    }
}

// ---------------- node kernel: feat = relu(agg/deg + x @ Ws + bs); score += segmean(feat@Wc+bc)
template <int FIN, int F>
__global__ __launch_bounds__(256) void node_kernel(
    const float* __restrict__ xin, const float* __restrict__ agg,
    const float* __restrict__ Ws, const float* __restrict__ bs,
    const float* __restrict__ Wc, const float* __restrict__ bc,
    const int* __restrict__ gid, const float* __restrict__ deg,
    const float* __restrict__ gcnt,
    float* __restrict__ fout, float* __restrict__ score)
{
    constexpr int P = F / 64;
    extern __shared__ float smem[];
    float* Ws_s = smem;                  // FIN*F
    float* Wc_s = Ws_s + FIN * F;        // F
    float* in_s = Wc_s + F;              // 32*FIN

    const int tid = threadIdx.x;
    const int w = tid >> 5, lane = tid & 31;

    for (int i = tid; i < FIN * F; i += 256) Ws_s[i] = Ws[i];
    for (int i = tid; i < F; i += 256) Wc_s[i] = Wc[i];
    float bsr[P][2];
    #pragma unroll
    for (int p = 0; p < P; p++) {
        bsr[p][0] = bs[p * 64 + lane * 2];
        bsr[p][1] = bs[p * 64 + lane * 2 + 1];
    }
    const float bcv = bc[0];
    __syncthreads();

    const int nTiles = (NN + 31) / 32;
    for (int tile = blockIdx.x; tile < nTiles; tile += gridDim.x) {
        const int base = tile * 32;
        __syncthreads();
        for (int i = tid; i < 32 * (FIN / 4); i += 256) {
            int nl = i / (FIN / 4);
            int k4 = (i % (FIN / 4)) * 4;
            int n = base + nl;
            float4 v = make_float4(0.f, 0.f, 0.f, 0.f);
            if (n < NN) v = *(const float4*)&xin[(size_t)n * FIN + k4];
            *(float4*)&in_s[nl * FIN + k4] = v;
        }
        __syncthreads();

        unsigned long long acc[4][P];
        #pragma unroll
        for (int e = 0; e < 4; e++)
            #pragma unroll
            for (int p = 0; p < P; p++) acc[e][p] = 0ull;

        const unsigned long long* Ws2 = (const unsigned long long*)Ws_s;
        const float* in0 = &in_s[(w * 4) * FIN];

        for (int k4 = 0; k4 < FIN; k4 += 4) {
            float4 vv[4];
            #pragma unroll
            for (int e = 0; e < 4; e++)
                vv[e] = *(const float4*)&in0[e * FIN + k4];
            #pragma unroll
            for (int kk = 0; kk < 4; kk++) {
                const int k = k4 + kk;
                unsigned long long dup[4];
                #pragma unroll
                for (int e = 0; e < 4; e++) {
                    float v = (kk == 0) ? vv[e].x : (kk == 1) ? vv[e].y
                             : (kk == 2) ? vv[e].z : vv[e].w;
                    DUP2(dup[e], v);
                }
                #pragma unroll
                for (int p = 0; p < P; p++) {
                    unsigned long long w2 = Ws2[k * (F / 2) + p * 32 + lane];
                    #pragma unroll
                    for (int e = 0; e < 4; e++) FMA2(acc[e][p], dup[e], w2, acc[e][p]);
                }
            }
        }

        #pragma unroll
        for (int e = 0; e < 4; e++) {
            int n = base + w * 4 + e;
            if (n >= NN) continue;
            float inv = 1.0f / fmaxf(deg[n], 1.0f);
            const float* arow = agg + (size_t)n * F;
            float* frow = fout + (size_t)n * F;
            float cpart = 0.0f;
            #pragma unroll
            for (int p = 0; p < P; p++) {
                int c0 = p * 64 + lane * 2;
                float2 av = *(const float2*)&arow[c0];
                float lo = fmaxf(av.x * inv + __uint_as_float((unsigned)acc[e][p]) + bsr[p][0], 0.0f);
                float hi = fmaxf(av.y * inv + __uint_as_float((unsigned)(acc[e][p] >> 32)) + bsr[p][1], 0.0f);
                float2 ov; ov.x = lo; ov.y = hi;
                *(float2*)&frow[c0] = ov;
                cpart += lo * Wc_s[c0] + hi * Wc_s[c0 + 1];
            }
            #pragma unroll
            for (int off = 16; off; off >>= 1)
                cpart += __shfl_xor_sync(0xFFFFFFFFu, cpart, off);
            if (lane == 0) {
                int g = gid[n];
                atomicAdd(&score[g], (cpart + bcv) / fmaxf(gcnt[g], 1.0f));
            }
        }
    }
}

// ---------------- host side ----------------
template <typename Kern>
static int grid_for(Kern k, int smem_bytes, int tiles, int nsm) {
    cudaFuncSetAttribute(k, cudaFuncAttributeMaxDynamicSharedMemorySize, smem_bytes);
    int occ = 1;
    cudaOccupancyMaxActiveBlocksPerMultiprocessor(&occ, k, 256, smem_bytes);
    if (occ < 1) occ = 1;
    int g = nsm * occ;
    if (g > tiles) g = tiles;
    return g;
}

template <int FIN, int F>
static void run_layer(const float* xin, const float* efeat, const int* src, const int* dst,
                      const int* gid, const float* const* Wl,
                      float* agg, float* fout, float* score,
                      float* deg, float* gcnt, int nsm)
{
    constexpr int K = FIN + EFD;
    const int smem_e = (K * F + 64 * K) * 4 + 128 * 4;
    const int smem_n = (FIN * F + F + 32 * FIN) * 4;

    cudaMemsetAsync(agg, 0, (size_t)NN * F * sizeof(float));
    int ge = grid_for(edge_kernel<FIN, F>, smem_e, EE / 64, nsm);
    edge_kernel<FIN, F><<<ge, 256, smem_e>>>(xin, efeat, src, dst, Wl[0], Wl[1], agg);
    int gn = grid_for(node_kernel<FIN, F>, smem_n, (NN + 31) / 32, nsm);
    node_kernel<FIN, F><<<gn, 256, smem_n>>>(xin, agg, Wl[2], Wl[3], Wl[4], Wl[5],
                                             gid, deg, gcnt, fout, score);
}

extern "C" void kernel_launch(void* const* d_in, const int* in_sizes, int n_in,
                              void* d_out, int out_size)
{
    const float* x   = (const float*)d_in[0];
    const float* e   = (const float*)d_in[1];
    const int*   src = (const int*)d_in[2];
    const int*   dst = (const int*)d_in[3];
    const int*   gid = (const int*)d_in[4];
    const float* W[4][6];
    for (int l = 0; l < 4; l++)
        for (int j = 0; j < 6; j++)
            W[l][j] = (const float*)d_in[5 + l * 6 + j];
    float* score = (float*)d_out;

    float *bufA, *bufB, *agg, *deg, *gcnt;
    cudaGetSymbolAddress((void**)&bufA, g_bufA);
    cudaGetSymbolAddress((void**)&bufB, g_bufB);
    cudaGetSymbolAddress((void**)&agg, g_agg);
    cudaGetSymbolAddress((void**)&deg, g_deg);
    cudaGetSymbolAddress((void**)&gcnt, g_gcnt);

    int nsm = 148;
    cudaDeviceGetAttribute(&nsm, cudaDevAttrMultiProcessorCount, 0);

    cudaMemsetAsync(deg, 0, NN * sizeof(float));
    cudaMemsetAsync(gcnt, 0, GG * sizeof(float));
    cudaMemsetAsync(score, 0, GG * sizeof(float));
    count_kernel<<<(EE + 255) / 256, 256>>>(dst, gid, deg, gcnt);

    run_layer<32, 64>  (x,    e, src, dst, gid, W[0], agg, bufA, score, deg, gcnt, nsm);
    run_layer<64, 128> (bufA, e, src, dst, gid, W[1], agg, bufB, score, deg, gcnt, nsm);
    run_layer<128, 128>(bufB, e, src, dst, gid, W[2], agg, bufA, score, deg, gcnt, nsm);
    run_layer<128, 256>(bufA, e, src, dst, gid, W[3], agg, bufB, score, deg, gcnt, nsm);
}

// round 5
// speedup vs baseline: 1.4128x; 1.2494x over previous
#include <cuda_runtime.h>
#include <cstdint>

#define NN 50000
#define EE 800000
#define GG 512
#define EFD 16

// ---------------- scratch (no allocations allowed) ----------------
__device__ float g_bufA[NN * 256];
__device__ float g_bufB[NN * 256];
__device__ float g_agg[NN * 256];
__device__ float g_deg[NN];
__device__ float g_gcnt[GG];

// ---------------- helpers ----------------
__device__ __forceinline__ uint32_t f2tf32(float x) {
    uint32_t r;
    asm("cvt.rna.tf32.f32 %0, %1;" : "=r"(r) : "f"(x));
    return r;
}

// D += A(16x8,row) * B(8x8,col), tf32 inputs, f32 accum
__device__ __forceinline__ void mma_tf32(float* d, const uint32_t* a, const uint32_t* b) {
    asm volatile(
        "mma.sync.aligned.m16n8k8.row.col.f32.tf32.tf32.f32 "
        "{%0,%1,%2,%3}, {%4,%5,%6,%7}, {%8,%9}, {%0,%1,%2,%3};"
        : "+f"(d[0]), "+f"(d[1]), "+f"(d[2]), "+f"(d[3])
        : "r"(a[0]), "r"(a[1]), "r"(a[2]), "r"(a[3]), "r"(b[0]), "r"(b[1]));
}

// packed f32x2 FMA (sm_103a pipe, plain PTX)
#define FMA2(d, a, b, c) \
    asm("fma.rn.f32x2 %0, %1, %2, %3;" : "=l"(d) : "l"(a), "l"(b), "l"(c))
#define DUP2(d, s) \
    asm("mov.b64 %0, {%1, %1};" : "=l"(d) : "r"(__float_as_uint(s)))

__global__ void count_kernel(const int* __restrict__ dst, const int* __restrict__ gid,
                             float* __restrict__ deg, float* __restrict__ gcnt) {
    int i = blockIdx.x * blockDim.x + threadIdx.x;
    if (i < EE) atomicAdd(&deg[dst[i]], 1.0f);
    if (i < NN) atomicAdd(&gcnt[gid[i]], 1.0f);
}

// ---------------- tensor-core edge kernel (mma.sync tf32) ----------------
// agg[dst] += relu(concat(x[src], e) @ Wm[:, col_off:col_off+FK] + bm[col_off:]).
// Tile = 128 edges. A and W staged in SMEM pre-permuted into m16n8k8 fragment order.
// 8 warps: warp w -> rows (w&3)*32..+31, cols (w>>2)*(FK/2)..+FK/2-1.
template <int FIN, int K, int F, int FK>
__global__ __launch_bounds__(256, 1)
void edge_mma_kernel(const float* __restrict__ xin, const float* __restrict__ efeat,
                     const int* __restrict__ src, const int* __restrict__ dst,
                     const float* __restrict__ Wm, const float* __restrict__ bm,
                     float* __restrict__ agg, int col_off)
{
    constexpr int KC8 = K / 8;      // K is a multiple of 8 for all layers (48/80/144)
    constexpr int NT = FK / 16;     // n8-tiles per warp (FK=128 -> 8, FK=64 -> 4)

    // smem byte offsets
    constexpr int BIAS_OFF = 0;                    // FK floats
    constexpr int SSRC_OFF = 1024;                 // 128 ints
    constexpr int SDST_OFF = 1536;                 // 128 ints
    constexpr int A_OFF = 2048;                    // 128*K u32 (fragment-permuted)
    constexpr int W_OFF = 2048 + 512 * K;          // K*FK u32 (fragment-permuted)

    extern __shared__ char smem[];
    float* bias_s = (float*)(smem + BIAS_OFF);
    int* ssrc = (int*)(smem + SSRC_OFF);
    int* sdst = (int*)(smem + SDST_OFF);
    uint32_t* Ap = (uint32_t*)(smem + A_OFF);
    uint32_t* Wp = (uint32_t*)(smem + W_OFF);

    const int tid = threadIdx.x;
    const int w = tid >> 5, lane = tid & 31;
    const int rw = w & 3, cw = w >> 2;
    const int g = lane >> 2, tg = lane & 3;

    for (int i = tid; i < FK; i += 256) bias_s[i] = bm[col_off + i];

    // stage weights in B-fragment order:
    // value W[k][n] -> Wp[((T*KC8 + kc)*32 + (n%8)*4 + (k%4))*2 + ((k>>2)&1)]
    for (int i = tid; i < K * FK; i += 256) {
        int k = i / FK, n = i % FK;
        uint32_t val = f2tf32(Wm[k * F + col_off + n]);
        int T = n >> 3, kc = k >> 3;
        Wp[((T * KC8 + kc) * 32 + (n & 7) * 4 + (k & 3)) * 2 + ((k >> 2) & 1)] = val;
    }

    // per-lane bias regs for owned columns
    float br[NT][2];
    #pragma unroll
    for (int t = 0; t < NT; t++) {
        int n = cw * (FK / 2) + t * 8 + tg * 2;
        br[t][0] = bm[col_off + n];
        br[t][1] = bm[col_off + n + 1];
    }
    __syncthreads();

    const int nTiles = EE / 128;  // 6250, exact
    for (int tile = blockIdx.x; tile < nTiles; tile += gridDim.x) {
        const int base = tile * 128;
        __syncthreads();  // prior epilogue (sdst reads) done before overwrite
        if (tid < 128) { ssrc[tid] = src[base + tid]; sdst[tid] = dst[base + tid]; }
        __syncthreads();

        // gather edge rows, convert to tf32, write in A-fragment order:
        // value A[row][k] -> Ap[((rg*KC8 + kc)*32 + (row%8)*4 + (k%4))*4 + f],
        // f = ((row>>3)&1) + 2*((k>>2)&1)
        for (int i = tid; i < 128 * (K / 4); i += 256) {
            int row = i / (K / 4);
            int k4 = (i % (K / 4)) * 4;
            float4 v;
            if (k4 < FIN) v = *(const float4*)&xin[(size_t)ssrc[row] * FIN + k4];
            else          v = *(const float4*)&efeat[(size_t)(base + row) * EFD + (k4 - FIN)];
            int rg = row >> 4, kc = k4 >> 3;
            int f = ((row >> 3) & 1) + 2 * ((k4 >> 2) & 1);
            uint32_t* p = Ap + ((rg * KC8 + kc) * 32 + (row & 7) * 4) * 4 + f;
            p[0]  = f2tf32(v.x);
            p[4]  = f2tf32(v.y);
            p[8]  = f2tf32(v.z);
            p[12] = f2tf32(v.w);
        }
        __syncthreads();

        // mainloop: pure LDS + HMMA
        float acc[2][NT][4];
        #pragma unroll
        for (int mi = 0; mi < 2; mi++)
            #pragma unroll
            for (int t = 0; t < NT; t++)
                #pragma unroll
                for (int j = 0; j < 4; j++) acc[mi][t][j] = 0.0f;

        for (int kc = 0; kc < KC8; kc++) {
            uint4 a[2];
            #pragma unroll
            for (int mi = 0; mi < 2; mi++)
                a[mi] = *(const uint4*)&Ap[(((rw * 2 + mi) * KC8 + kc) * 32 + lane) * 4];
            #pragma unroll
            for (int t = 0; t < NT; t++) {
                int T = cw * NT + t;
                uint2 b = *(const uint2*)&Wp[((T * KC8 + kc) * 32 + lane) * 2];
                mma_tf32(acc[0][t], (const uint32_t*)&a[0], (const uint32_t*)&b);
                mma_tf32(acc[1][t], (const uint32_t*)&a[1], (const uint32_t*)&b);
            }
        }

        // epilogue: bias + relu + atomic scatter (zero-skip)
        #pragma unroll
        for (int mi = 0; mi < 2; mi++) {
            int r0 = rw * 32 + mi * 16 + g;
            int r1 = r0 + 8;
            float* row0 = agg + (size_t)sdst[r0] * F + col_off;
            float* row1 = agg + (size_t)sdst[r1] * F + col_off;
            #pragma unroll
            for (int t = 0; t < NT; t++) {
                int n = cw * (FK / 2) + t * 8 + tg * 2;
                float v0 = acc[mi][t][0] + br[t][0];
                float v1 = acc[mi][t][1] + br[t][1];
                float v2 = acc[mi][t][2] + br[t][0];
                float v3 = acc[mi][t][3] + br[t][1];
                if (v0 > 0.0f) atomicAdd(&row0[n], v0);
                if (v1 > 0.0f) atomicAdd(&row0[n + 1], v1);
                if (v2 > 0.0f) atomicAdd(&row1[n], v2);
                if (v3 > 0.0f) atomicAdd(&row1[n + 1], v3);
            }
        }
    }
}

// ---------------- node kernel (FFMA f32x2) ----------------
template <int FIN, int F>
__global__ __launch_bounds__(256) void node_kernel(
    const float* __restrict__ xin, const float* __restrict__ agg,
    const float* __restrict__ Ws, const float* __restrict__ bs,
    const float* __restrict__ Wc, const float* __restrict__ bc,
    const int* __restrict__ gid, const float* __restrict__ deg,
    const float* __restrict__ gcnt,
    float* __restrict__ fout, float* __restrict__ score)
{
    constexpr int P = F / 64;
    extern __shared__ float smemf[];
    float* Ws_s = smemf;
    float* Wc_s = Ws_s + FIN * F;
    float* in_s = Wc_s + F;

    const int tid = threadIdx.x;
    const int w = tid >> 5, lane = tid & 31;

    for (int i = tid; i < FIN * F; i += 256) Ws_s[i] = Ws[i];
    for (int i = tid; i < F; i += 256) Wc_s[i] = Wc[i];
    float bsr[P][2];
    #pragma unroll
    for (int p = 0; p < P; p++) {
        bsr[p][0] = bs[p * 64 + lane * 2];
        bsr[p][1] = bs[p * 64 + lane * 2 + 1];
    }
    const float bcv = bc[0];
    __syncthreads();

    const int nTiles = (NN + 31) / 32;
    for (int tile = blockIdx.x; tile < nTiles; tile += gridDim.x) {
        const int base = tile * 32;
        __syncthreads();
        for (int i = tid; i < 32 * (FIN / 4); i += 256) {
            int nl = i / (FIN / 4);
            int k4 = (i % (FIN / 4)) * 4;
            int n = base + nl;
            float4 v = make_float4(0.f, 0.f, 0.f, 0.f);
            if (n < NN) v = *(const float4*)&xin[(size_t)n * FIN + k4];
            *(float4*)&in_s[nl * FIN + k4] = v;
        }
        __syncthreads();

        unsigned long long acc[4][P];
        #pragma unroll
        for (int e = 0; e < 4; e++)
            #pragma unroll
            for (int p = 0; p < P; p++) acc[e][p] = 0ull;

        const unsigned long long* Ws2 = (const unsigned long long*)Ws_s;
        const float* in0 = &in_s[(w * 4) * FIN];

        for (int k4 = 0; k4 < FIN; k4 += 4) {
            float4 vv[4];
            #pragma unroll
            for (int e = 0; e < 4; e++)
                vv[e] = *(const float4*)&in0[e * FIN + k4];
            #pragma unroll
            for (int kk = 0; kk < 4; kk++) {
                const int k = k4 + kk;
                unsigned long long dup[4];
                #pragma unroll
                for (int e = 0; e < 4; e++) {
                    float v = (kk == 0) ? vv[e].x : (kk == 1) ? vv[e].y
                             : (kk == 2) ? vv[e].z : vv[e].w;
                    DUP2(dup[e], v);
                }
                #pragma unroll
                for (int p = 0; p < P; p++) {
                    unsigned long long w2 = Ws2[k * (F / 2) + p * 32 + lane];
                    #pragma unroll
                    for (int e = 0; e < 4; e++) FMA2(acc[e][p], dup[e], w2, acc[e][p]);
                }
            }
        }

        #pragma unroll
        for (int e = 0; e < 4; e++) {
            int n = base + w * 4 + e;
            if (n >= NN) continue;
            float inv = 1.0f / fmaxf(deg[n], 1.0f);
            const float* arow = agg + (size_t)n * F;
            float* frow = fout + (size_t)n * F;
            float cpart = 0.0f;
            #pragma unroll
            for (int p = 0; p < P; p++) {
                int c0 = p * 64 + lane * 2;
                float2 av = *(const float2*)&arow[c0];
                float lo = fmaxf(av.x * inv + __uint_as_float((unsigned)acc[e][p]) + bsr[p][0], 0.0f);
                float hi = fmaxf(av.y * inv + __uint_as_float((unsigned)(acc[e][p] >> 32)) + bsr[p][1], 0.0f);
                float2 ov; ov.x = lo; ov.y = hi;
                *(float2*)&frow[c0] = ov;
                cpart += lo * Wc_s[c0] + hi * Wc_s[c0 + 1];
            }
            #pragma unroll
            for (int off = 16; off; off >>= 1)
                cpart += __shfl_xor_sync(0xFFFFFFFFu, cpart, off);
            if (lane == 0) {
                int gg = gid[n];
                atomicAdd(&score[gg], (cpart + bcv) / fmaxf(gcnt[gg], 1.0f));
            }
        }
    }
}

// ---------------- host side ----------------
template <typename Kern>
static int grid_for(Kern k, int smem_bytes, int tiles, int nsm) {
    cudaFuncSetAttribute(k, cudaFuncAttributeMaxDynamicSharedMemorySize, smem_bytes);
    int occ = 1;
    cudaOccupancyMaxActiveBlocksPerMultiprocessor(&occ, k, 256, smem_bytes);
    if (occ < 1) occ = 1;
    int g = nsm * occ;
    if (g > tiles) g = tiles;
    return g;
}

template <int FIN, int K, int F, int FK>
static void launch_edge(const float* xin, const float* efeat, const int* src, const int* dst,
                        const float* Wm, const float* bm, float* agg, int col_off, int nsm)
{
    const int smem = 2048 + 128 * K * 4 + K * FK * 4;
    int g = grid_for(edge_mma_kernel<FIN, K, F, FK>, smem, EE / 128, nsm);
    edge_mma_kernel<FIN, K, F, FK><<<g, 256, smem>>>(xin, efeat, src, dst, Wm, bm, agg, col_off);
}

template <int FIN, int F>
static void launch_node(const float* xin, const float* agg, const float* const* Wl,
                        const int* gid, const float* deg, const float* gcnt,
                        float* fout, float* score, int nsm)
{
    const int smem_n = (FIN * F + F + 32 * FIN) * 4;
    int gn = grid_for(node_kernel<FIN, F>, smem_n, (NN + 31) / 32, nsm);
    node_kernel<FIN, F><<<gn, 256, smem_n>>>(xin, agg, Wl[2], Wl[3], Wl[4], Wl[5],
                                             gid, deg, gcnt, fout, score);
}

extern "C" void kernel_launch(void* const* d_in, const int* in_sizes, int n_in,
                              void* d_out, int out_size)
{
    const float* x   = (const float*)d_in[0];
    const float* e   = (const float*)d_in[1];
    const int*   src = (const int*)d_in[2];
    const int*   dst = (const int*)d_in[3];
    const int*   gid = (const int*)d_in[4];
    const float* W[4][6];
    for (int l = 0; l < 4; l++)
        for (int j = 0; j < 6; j++)
            W[l][j] = (const float*)d_in[5 + l * 6 + j];
    float* score = (float*)d_out;

    float *bufA, *bufB, *agg, *deg, *gcnt;
    cudaGetSymbolAddress((void**)&bufA, g_bufA);
    cudaGetSymbolAddress((void**)&bufB, g_bufB);
    cudaGetSymbolAddress((void**)&agg, g_agg);
    cudaGetSymbolAddress((void**)&deg, g_deg);
    cudaGetSymbolAddress((void**)&gcnt, g_gcnt);

    int nsm = 148;
    cudaDeviceGetAttribute(&nsm, cudaDevAttrMultiProcessorCount, 0);

    cudaMemsetAsync(deg, 0, NN * sizeof(float));
    cudaMemsetAsync(gcnt, 0, GG * sizeof(float));
    cudaMemsetAsync(score, 0, GG * sizeof(float));
    count_kernel<<<(EE + 255) / 256, 256>>>(dst, gid, deg, gcnt);

    // layer 0: K=48, F=64
    cudaMemsetAsync(agg, 0, (size_t)NN * 64 * sizeof(float));
    launch_edge<32, 48, 64, 64>(x, e, src, dst, W[0][0], W[0][1], agg, 0, nsm);
    launch_node<32, 64>(x, agg, W[0], gid, deg, gcnt, bufA, score, nsm);

    // layer 1: K=80, F=128
    cudaMemsetAsync(agg, 0, (size_t)NN * 128 * sizeof(float));
    launch_edge<64, 80, 128, 128>(bufA, e, src, dst, W[1][0], W[1][1], agg, 0, nsm);
    launch_node<64, 128>(bufA, agg, W[1], gid, deg, gcnt, bufB, score, nsm);

    // layer 2: K=144, F=128
    cudaMemsetAsync(agg, 0, (size_t)NN * 128 * sizeof(float));
    launch_edge<128, 144, 128, 128>(bufB, e, src, dst, W[2][0], W[2][1], agg, 0, nsm);
    launch_node<128, 128>(bufB, agg, W[2], gid, deg, gcnt, bufA, score, nsm);

    // layer 3: K=144, F=256 (two FK=128 halves)
    cudaMemsetAsync(agg, 0, (size_t)NN * 256 * sizeof(float));
    launch_edge<128, 144, 256, 128>(bufA, e, src, dst, W[3][0], W[3][1], agg, 0, nsm);
    launch_edge<128, 144, 256, 128>(bufA, e, src, dst, W[3][0], W[3][1], agg, 128, nsm);
    launch_node<128, 256>(bufA, agg, W[3], gid, deg, gcnt, bufB, score, nsm);
}

// round 6
// speedup vs baseline: 1.7944x; 1.2701x over previous
#include <cuda_runtime.h>
#include <cstdint>

#define NN 50000
#define EE 800000
#define GG 512
#define EFD 16

// ---------------- scratch (no allocations allowed) ----------------
__device__ float g_bufA[NN * 256];
__device__ float g_bufB[NN * 256];
__device__ float g_agg[NN * 256];
__device__ float g_deg[NN];
__device__ float g_gcnt[GG];

// ---------------- helpers ----------------
__device__ __forceinline__ uint32_t f2tf32(float x) {
    uint32_t r;
    asm("cvt.rna.tf32.f32 %0, %1;" : "=r"(r) : "f"(x));
    return r;
}
__device__ __forceinline__ uint32_t smem_u32(const void* p) {
    uint32_t a;
    asm("{ .reg .u64 t; cvta.to.shared.u64 t, %1; cvt.u32.u64 %0, t; }" : "=r"(a) : "l"(p));
    return a;
}
__device__ __forceinline__ void cp16(uint32_t saddr, const void* gaddr) {
    asm volatile("cp.async.ca.shared.global [%0], [%1], 16;" :: "r"(saddr), "l"(gaddr) : "memory");
}
#define CP_COMMIT() asm volatile("cp.async.commit_group;" ::: "memory")
#define CP_WAIT(n)  asm volatile("cp.async.wait_group %0;" :: "n"(n) : "memory")

// D += A(16x8,row) * B(8x8,col), tf32 inputs, f32 accum
__device__ __forceinline__ void mma_tf32(float* d, const uint32_t* a, const uint32_t* b) {
    asm volatile(
        "mma.sync.aligned.m16n8k8.row.col.f32.tf32.tf32.f32 "
        "{%0,%1,%2,%3}, {%4,%5,%6,%7}, {%8,%9}, {%0,%1,%2,%3};"
        : "+f"(d[0]), "+f"(d[1]), "+f"(d[2]), "+f"(d[3])
        : "r"(a[0]), "r"(a[1]), "r"(a[2]), "r"(a[3]), "r"(b[0]), "r"(b[1]));
}

// packed f32x2 FMA (plain PTX, sm_103 ok)
#define FMA2(d, a, b, c) \
    asm("fma.rn.f32x2 %0, %1, %2, %3;" : "=l"(d) : "l"(a), "l"(b), "l"(c))
#define DUP2(d, s) \
    asm("mov.b64 %0, {%1, %1};" : "=l"(d) : "r"(__float_as_uint(s)))

__global__ void count_kernel(const int* __restrict__ dst, const int* __restrict__ gid,
                             float* __restrict__ deg, float* __restrict__ gcnt) {
    int i = blockIdx.x * blockDim.x + threadIdx.x;
    if (i < EE) atomicAdd(&deg[dst[i]], 1.0f);
    if (i < NN) atomicAdd(&gcnt[gid[i]], 1.0f);
}

// ---------------- pipelined tensor-core edge kernel ----------------
// agg[dst] += relu(concat(x[src], e) @ Wm[:, col_off:+FK] + bm).
// Tile = 128 edges; block = 128 threads = 4 warps in a 2x2 grid of 64 x (FK/2) warp tiles.
// A double-buffered row-major in SMEM via cp.async (KP = K+4 kills bank conflicts),
// W pre-permuted into m16n8k8 B-fragment order (tf32) once per launch.
template <int FIN, int K, int F, int FK>
__global__ __launch_bounds__(128, 1)
void edge_mma_kernel(const float* __restrict__ xin, const float* __restrict__ efeat,
                     const int* __restrict__ src, const int* __restrict__ dst,
                     const float* __restrict__ Wm, const float* __restrict__ bm,
                     float* __restrict__ agg, int col_off)
{
    constexpr int KP = K + 4;            // floats per A row; KP % 32 == 20 -> conflict-free frags
    constexpr int KC8 = K / 8;
    constexpr int NT = FK / 16;          // n8 tiles per warp
    constexpr int W_U32 = K * FK;
    constexpr int A_F32 = 128 * KP;

    extern __shared__ char smem[];
    uint32_t* Wp = (uint32_t*)smem;                                    // W_U32
    float* Abuf = (float*)(smem + (size_t)W_U32 * 4);                  // 2 * A_F32
    int* sdst = (int*)(smem + (size_t)W_U32 * 4 + (size_t)2 * A_F32 * 4);  // 2 * 128

    const int tid = threadIdx.x;
    const int w = tid >> 5, lane = tid & 31;
    const int wm = w >> 1, wn = w & 1;
    const int g = lane >> 2, tg = lane & 3;
    const uint32_t sbA = smem_u32(Abuf);

    // stage weights in B-fragment order (tf32)
    for (int i = tid; i < K * FK; i += 128) {
        int k = i / FK, n = i % FK;
        uint32_t val = f2tf32(Wm[k * F + col_off + n]);
        int T = n >> 3, kc = k >> 3;
        Wp[((T * KC8 + kc) * 32 + (n & 7) * 4 + (k & 3)) * 2 + ((k >> 2) & 1)] = val;
    }
    float br[NT][2];
    #pragma unroll
    for (int t = 0; t < NT; t++) {
        int n = wn * (FK / 2) + t * 8 + tg * 2;
        br[t][0] = bm[col_off + n];
        br[t][1] = bm[col_off + n + 1];
    }

    const int nTiles = EE / 128;  // 6250, exact
    const int stride = gridDim.x;

    // gather: issue cp.async for (tile -> buf) using prefetched srow/sd
    auto gather = [&](int tile, int buf, int srow, int sd) {
        int base = tile * 128;
        sdst[buf * 128 + tid] = sd;
        uint32_t arow = sbA + (uint32_t)(buf * A_F32 + tid * KP) * 4;
        const char* xr = (const char*)(xin + (size_t)srow * FIN);
        #pragma unroll
        for (int c = 0; c < FIN / 4; c++) cp16(arow + c * 16, xr + c * 16);
        const char* er = (const char*)(efeat + (size_t)(base + tid) * EFD);
        #pragma unroll
        for (int c = 0; c < 4; c++) cp16(arow + FIN * 4 + c * 16, er + c * 16);
    };

    // preamble: fetch indices for tile0, gather it, prefetch indices for tile1
    int t0 = blockIdx.x;
    int ps = src[t0 * 128 + tid];
    int pd = dst[t0 * 128 + tid];
    gather(t0, 0, ps, pd);
    CP_COMMIT();
    int nxt0 = t0 + stride;
    if (nxt0 < nTiles) { ps = src[nxt0 * 128 + tid]; pd = dst[nxt0 * 128 + tid]; }

    int cur = 0;
    for (int tile = t0; tile < nTiles; tile += stride) {
        int nxt = tile + stride;
        if (nxt < nTiles) {
            gather(nxt, cur ^ 1, ps, pd);
            CP_COMMIT();
            int nn2 = nxt + stride;
            if (nn2 < nTiles) { ps = src[nn2 * 128 + tid]; pd = dst[nn2 * 128 + tid]; }
            CP_WAIT(1);
        } else {
            CP_WAIT(0);
        }
        __syncthreads();   // buf[cur] visible to all

        // ---- MMA mainloop on Abuf[cur] ----
        float acc[4][NT][4];
        #pragma unroll
        for (int mi = 0; mi < 4; mi++)
            #pragma unroll
            for (int t = 0; t < NT; t++)
                #pragma unroll
                for (int j = 0; j < 4; j++) acc[mi][t][j] = 0.0f;

        const float* A0 = Abuf + cur * A_F32;
        for (int kc = 0; kc < KC8; kc++) {
            uint2 b[NT];
            #pragma unroll
            for (int t = 0; t < NT; t++)
                b[t] = *(const uint2*)&Wp[(((wn * NT + t) * KC8 + kc) * 32 + lane) * 2];
            #pragma unroll
            for (int mi = 0; mi < 4; mi++) {
                const float* ar = A0 + (wm * 64 + mi * 16 + g) * KP + kc * 8 + tg;
                uint32_t a[4];
                a[0] = f2tf32(ar[0]);
                a[1] = f2tf32(ar[8 * KP]);
                a[2] = f2tf32(ar[4]);
                a[3] = f2tf32(ar[8 * KP + 4]);
                #pragma unroll
                for (int t = 0; t < NT; t++)
                    mma_tf32(acc[mi][t], a, (const uint32_t*)&b[t]);
            }
        }

        // ---- epilogue: bias + relu + atomic scatter (zero-skip) ----
        #pragma unroll
        for (int mi = 0; mi < 4; mi++) {
            int r0 = wm * 64 + mi * 16 + g;
            float* row0 = agg + (size_t)sdst[cur * 128 + r0] * F + col_off;
            float* row1 = agg + (size_t)sdst[cur * 128 + r0 + 8] * F + col_off;
            #pragma unroll
            for (int t = 0; t < NT; t++) {
                int n = wn * (FK / 2) + t * 8 + tg * 2;
                float v0 = acc[mi][t][0] + br[t][0];
                float v1 = acc[mi][t][1] + br[t][1];
                float v2 = acc[mi][t][2] + br[t][0];
                float v3 = acc[mi][t][3] + br[t][1];
                if (v0 > 0.0f) atomicAdd(&row0[n], v0);
                if (v1 > 0.0f) atomicAdd(&row0[n + 1], v1);
                if (v2 > 0.0f) atomicAdd(&row1[n], v2);
                if (v3 > 0.0f) atomicAdd(&row1[n + 1], v3);
            }
        }
        __syncthreads();   // all reads of buf[cur]/sdst[cur] done before reuse
        cur ^= 1;
    }
}

// ---------------- node kernel (FFMA f32x2) ----------------
template <int FIN, int F>
__global__ __launch_bounds__(256) void node_kernel(
    const float* __restrict__ xin, const float* __restrict__ agg,
    const float* __restrict__ Ws, const float* __restrict__ bs,
    const float* __restrict__ Wc, const float* __restrict__ bc,
    const int* __restrict__ gid, const float* __restrict__ deg,
    const float* __restrict__ gcnt,
    float* __restrict__ fout, float* __restrict__ score)
{
    constexpr int P = F / 64;
    extern __shared__ float smemf[];
    float* Ws_s = smemf;
    float* Wc_s = Ws_s + FIN * F;
    float* in_s = Wc_s + F;

    const int tid = threadIdx.x;
    const int w = tid >> 5, lane = tid & 31;

    for (int i = tid; i < FIN * F; i += 256) Ws_s[i] = Ws[i];
    for (int i = tid; i < F; i += 256) Wc_s[i] = Wc[i];
    float bsr[P][2];
    #pragma unroll
    for (int p = 0; p < P; p++) {
        bsr[p][0] = bs[p * 64 + lane * 2];
        bsr[p][1] = bs[p * 64 + lane * 2 + 1];
    }
    const float bcv = bc[0];
    __syncthreads();

    const int nTiles = (NN + 31) / 32;
    for (int tile = blockIdx.x; tile < nTiles; tile += gridDim.x) {
        const int base = tile * 32;
        __syncthreads();
        for (int i = tid; i < 32 * (FIN / 4); i += 256) {
            int nl = i / (FIN / 4);
            int k4 = (i % (FIN / 4)) * 4;
            int n = base + nl;
            float4 v = make_float4(0.f, 0.f, 0.f, 0.f);
            if (n < NN) v = *(const float4*)&xin[(size_t)n * FIN + k4];
            *(float4*)&in_s[nl * FIN + k4] = v;
        }
        __syncthreads();

        unsigned long long acc[4][P];
        #pragma unroll
        for (int e = 0; e < 4; e++)
            #pragma unroll
            for (int p = 0; p < P; p++) acc[e][p] = 0ull;

        const unsigned long long* Ws2 = (const unsigned long long*)Ws_s;
        const float* in0 = &in_s[(w * 4) * FIN];

        for (int k4 = 0; k4 < FIN; k4 += 4) {
            float4 vv[4];
            #pragma unroll
            for (int e = 0; e < 4; e++)
                vv[e] = *(const float4*)&in0[e * FIN + k4];
            #pragma unroll
            for (int kk = 0; kk < 4; kk++) {
                const int k = k4 + kk;
                unsigned long long dup[4];
                #pragma unroll
                for (int e = 0; e < 4; e++) {
                    float v = (kk == 0) ? vv[e].x : (kk == 1) ? vv[e].y
                             : (kk == 2) ? vv[e].z : vv[e].w;
                    DUP2(dup[e], v);
                }
                #pragma unroll
                for (int p = 0; p < P; p++) {
                    unsigned long long w2 = Ws2[k * (F / 2) + p * 32 + lane];
                    #pragma unroll
                    for (int e = 0; e < 4; e++) FMA2(acc[e][p], dup[e], w2, acc[e][p]);
                }
            }
        }

        #pragma unroll
        for (int e = 0; e < 4; e++) {
            int n = base + w * 4 + e;
            if (n >= NN) continue;
            float inv = 1.0f / fmaxf(deg[n], 1.0f);
            const float* arow = agg + (size_t)n * F;
            float* frow = fout + (size_t)n * F;
            float cpart = 0.0f;
            #pragma unroll
            for (int p = 0; p < P; p++) {
                int c0 = p * 64 + lane * 2;
                float2 av = *(const float2*)&arow[c0];
                float lo = fmaxf(av.x * inv + __uint_as_float((unsigned)acc[e][p]) + bsr[p][0], 0.0f);
                float hi = fmaxf(av.y * inv + __uint_as_float((unsigned)(acc[e][p] >> 32)) + bsr[p][1], 0.0f);
                float2 ov; ov.x = lo; ov.y = hi;
                *(float2*)&frow[c0] = ov;
                cpart += lo * Wc_s[c0] + hi * Wc_s[c0 + 1];
            }
            #pragma unroll
            for (int off = 16; off; off >>= 1)
                cpart += __shfl_xor_sync(0xFFFFFFFFu, cpart, off);
            if (lane == 0) {
                int gg = gid[n];
                atomicAdd(&score[gg], (cpart + bcv) / fmaxf(gcnt[gg], 1.0f));
            }
        }
    }
}

// ---------------- host side ----------------
template <typename Kern>
static int grid_for(Kern k, int smem_bytes, int tiles, int nsm, int block) {
    cudaFuncSetAttribute(k, cudaFuncAttributeMaxDynamicSharedMemorySize, smem_bytes);
    int occ = 1;
    cudaOccupancyMaxActiveBlocksPerMultiprocessor(&occ, k, block, smem_bytes);
    if (occ < 1) occ = 1;
    int g = nsm * occ;
    if (g > tiles) g = tiles;
    return g;
}

template <int FIN, int K, int F, int FK>
static void launch_edge(const float* xin, const float* efeat, const int* src, const int* dst,
                        const float* Wm, const float* bm, float* agg, int col_off, int nsm)
{
    constexpr int KP = K + 4;
    const int smem = K * FK * 4 + 2 * 128 * KP * 4 + 2 * 128 * 4;
    int g = grid_for(edge_mma_kernel<FIN, K, F, FK>, smem, EE / 128, nsm, 128);
    edge_mma_kernel<FIN, K, F, FK><<<g, 128, smem>>>(xin, efeat, src, dst, Wm, bm, agg, col_off);
}

template <int FIN, int F>
static void launch_node(const float* xin, const float* agg, const float* const* Wl,
                        const int* gid, const float* deg, const float* gcnt,
                        float* fout, float* score, int nsm)
{
    const int smem_n = (FIN * F + F + 32 * FIN) * 4;
    int gn = grid_for(node_kernel<FIN, F>, smem_n, (NN + 31) / 32, nsm, 256);
    node_kernel<FIN, F><<<gn, 256, smem_n>>>(xin, agg, Wl[2], Wl[3], Wl[4], Wl[5],
                                             gid, deg, gcnt, fout, score);
}

extern "C" void kernel_launch(void* const* d_in, const int* in_sizes, int n_in,
                              void* d_out, int out_size)
{
    const float* x   = (const float*)d_in[0];
    const float* e   = (const float*)d_in[1];
    const int*   src = (const int*)d_in[2];
    const int*   dst = (const int*)d_in[3];
    const int*   gid = (const int*)d_in[4];
    const float* W[4][6];
    for (int l = 0; l < 4; l++)
        for (int j = 0; j < 6; j++)
            W[l][j] = (const float*)d_in[5 + l * 6 + j];
    float* score = (float*)d_out;

    float *bufA, *bufB, *agg, *deg, *gcnt;
    cudaGetSymbolAddress((void**)&bufA, g_bufA);
    cudaGetSymbolAddress((void**)&bufB, g_bufB);
    cudaGetSymbolAddress((void**)&agg, g_agg);
    cudaGetSymbolAddress((void**)&deg, g_deg);
    cudaGetSymbolAddress((void**)&gcnt, g_gcnt);

    int nsm = 148;
    cudaDeviceGetAttribute(&nsm, cudaDevAttrMultiProcessorCount, 0);

    cudaMemsetAsync(deg, 0, NN * sizeof(float));
    cudaMemsetAsync(gcnt, 0, GG * sizeof(float));
    cudaMemsetAsync(score, 0, GG * sizeof(float));
    count_kernel<<<(EE + 255) / 256, 256>>>(dst, gid, deg, gcnt);

    // layer 0: K=48, F=64
    cudaMemsetAsync(agg, 0, (size_t)NN * 64 * sizeof(float));
    launch_edge<32, 48, 64, 64>(x, e, src, dst, W[0][0], W[0][1], agg, 0, nsm);
    launch_node<32, 64>(x, agg, W[0], gid, deg, gcnt, bufA, score, nsm);

    // layer 1: K=80, F=128
    cudaMemsetAsync(agg, 0, (size_t)NN * 128 * sizeof(float));
    launch_edge<64, 80, 128, 128>(bufA, e, src, dst, W[1][0], W[1][1], agg, 0, nsm);
    launch_node<64, 128>(bufA, agg, W[1], gid, deg, gcnt, bufB, score, nsm);

    // layer 2: K=144, F=128
    cudaMemsetAsync(agg, 0, (size_t)NN * 128 * sizeof(float));
    launch_edge<128, 144, 128, 128>(bufB, e, src, dst, W[2][0], W[2][1], agg, 0, nsm);
    launch_node<128, 128>(bufB, agg, W[2], gid, deg, gcnt, bufA, score, nsm);

    // layer 3: K=144, F=256 (two FK=128 halves)
    cudaMemsetAsync(agg, 0, (size_t)NN * 256 * sizeof(float));
    launch_edge<128, 144, 256, 128>(bufA, e, src, dst, W[3][0], W[3][1], agg, 0, nsm);
    launch_edge<128, 144, 256, 128>(bufA, e, src, dst, W[3][0], W[3][1], agg, 128, nsm);
    launch_node<128, 256>(bufA, agg, W[3], gid, deg, gcnt, bufB, score, nsm);
}

// round 7
// speedup vs baseline: 2.3059x; 1.2851x over previous
#include <cuda_runtime.h>
#include <cstdint>

#define NN 50000
#define EE 800000
#define GG 512
#define EFD 16

// ---------------- scratch (no allocations allowed) ----------------
__device__ float g_bufA[NN * 256];
__device__ float g_bufB[NN * 256];
__device__ float g_agg[NN * 256];
__device__ float g_deg[NN];
__device__ float g_gcnt[GG];

// ---------------- helpers ----------------
__device__ __forceinline__ uint32_t f2tf32(float x) {
    uint32_t r;
    asm("cvt.rna.tf32.f32 %0, %1;" : "=r"(r) : "f"(x));
    return r;
}
__device__ __forceinline__ uint32_t smem_u32(const void* p) {
    uint32_t a;
    asm("{ .reg .u64 t; cvta.to.shared.u64 t, %1; cvt.u32.u64 %0, t; }" : "=r"(a) : "l"(p));
    return a;
}
__device__ __forceinline__ void cp16(uint32_t saddr, const void* gaddr) {
    asm volatile("cp.async.ca.shared.global [%0], [%1], 16;" :: "r"(saddr), "l"(gaddr) : "memory");
}
#define CP_COMMIT() asm volatile("cp.async.commit_group;" ::: "memory")
#define CP_WAIT(n)  asm volatile("cp.async.wait_group %0;" :: "n"(n) : "memory")

// D += A(16x8,row) * B(8x8,col), tf32 inputs, f32 accum
__device__ __forceinline__ void mma_tf32(float* d, const uint32_t* a, const uint32_t* b) {
    asm volatile(
        "mma.sync.aligned.m16n8k8.row.col.f32.tf32.tf32.f32 "
        "{%0,%1,%2,%3}, {%4,%5,%6,%7}, {%8,%9}, {%0,%1,%2,%3};"
        : "+f"(d[0]), "+f"(d[1]), "+f"(d[2]), "+f"(d[3])
        : "r"(a[0]), "r"(a[1]), "r"(a[2]), "r"(a[3]), "r"(b[0]), "r"(b[1]));
}

// packed f32x2 FMA (plain PTX, sm_103 ok)
#define FMA2(d, a, b, c) \
    asm("fma.rn.f32x2 %0, %1, %2, %3;" : "=l"(d) : "l"(a), "l"(b), "l"(c))
#define DUP2(d, s) \
    asm("mov.b64 %0, {%1, %1};" : "=l"(d) : "r"(__float_as_uint(s)))

__global__ void count_kernel(const int* __restrict__ dst, const int* __restrict__ gid,
                             float* __restrict__ deg, float* __restrict__ gcnt) {
    int i = blockIdx.x * blockDim.x + threadIdx.x;
    if (i < EE) atomicAdd(&deg[dst[i]], 1.0f);
    if (i < NN) atomicAdd(&gcnt[gid[i]], 1.0f);
}

// ---------------- pipelined tensor-core edge kernel ----------------
// agg[dst] += relu(concat(x[src], e) @ Wm[:, col_off:+FK] + bm).
// Tile = 128 edges; block = 256 threads = 8 warps, 4x2 grid of 32 x (FK/2) warp tiles.
// A double-buffered row-major in SMEM via cp.async (KP = K+4 -> conflict-free fragments),
// W pre-permuted into m16n8k8 B-fragment order (tf32) once per launch.
template <int FIN, int K, int F, int FK>
__global__ __launch_bounds__(256)
void edge_mma_kernel(const float* __restrict__ xin, const float* __restrict__ efeat,
                     const int* __restrict__ src, const int* __restrict__ dst,
                     const float* __restrict__ Wm, const float* __restrict__ bm,
                     float* __restrict__ agg, int col_off)
{
    constexpr int KP = K + 4;            // KP % 32 == 20 -> conflict-free fragment LDS
    constexpr int KC8 = K / 8;
    constexpr int NT = FK / 16;          // n8 tiles per warp
    constexpr int W_U32 = K * FK;
    constexpr int A_F32 = 128 * KP;

    extern __shared__ char smem[];
    uint32_t* Wp = (uint32_t*)smem;                                        // W_U32
    float* Abuf = (float*)(smem + (size_t)W_U32 * 4);                      // 2 * A_F32
    int* sdst = (int*)(smem + (size_t)W_U32 * 4 + (size_t)2 * A_F32 * 4);  // 2 * 128

    const int tid = threadIdx.x;
    const int w = tid >> 5, lane = tid & 31;
    const int wm = w >> 1, wn = w & 1;           // 4 row-slabs x 2 col-halves
    const int g = lane >> 2, tg = lane & 3;
    const int row = tid >> 1, h = tid & 1;       // gather: 2 threads per edge row
    const uint32_t sbA = smem_u32(Abuf);

    // stage weights in B-fragment order (tf32)
    for (int i = tid; i < K * FK; i += 256) {
        int k = i / FK, n = i % FK;
        uint32_t val = f2tf32(Wm[k * F + col_off + n]);
        int T = n >> 3, kc = k >> 3;
        Wp[((T * KC8 + kc) * 32 + (n & 7) * 4 + (k & 3)) * 2 + ((k >> 2) & 1)] = val;
    }
    float br[NT][2];
    #pragma unroll
    for (int t = 0; t < NT; t++) {
        int n = wn * (FK / 2) + t * 8 + tg * 2;
        br[t][0] = bm[col_off + n];
        br[t][1] = bm[col_off + n + 1];
    }

    const int nTiles = EE / 128;  // 6250, exact
    const int stride = gridDim.x;

    // issue cp.async gather for (tile -> buf); srow/sd prefetched (pairs hold same row)
    auto gather = [&](int tile, int buf, int srow, int sd) {
        int base = tile * 128;
        if (h == 0) sdst[buf * 128 + row] = sd;
        uint32_t arow = sbA + (uint32_t)(buf * A_F32 + row * KP) * 4;
        const char* xr = (const char*)(xin + (size_t)srow * FIN);
        #pragma unroll
        for (int c = h; c < FIN / 4; c += 2) cp16(arow + c * 16, xr + c * 16);
        const char* er = (const char*)(efeat + (size_t)(base + row) * EFD);
        #pragma unroll
        for (int c = h; c < 4; c += 2) cp16(arow + FIN * 4 + c * 16, er + c * 16);
    };

    // preamble
    int t0 = blockIdx.x;
    int ps = src[t0 * 128 + row];
    int pd = dst[t0 * 128 + row];
    gather(t0, 0, ps, pd);
    CP_COMMIT();
    int nxt0 = t0 + stride;
    if (nxt0 < nTiles) { ps = src[nxt0 * 128 + row]; pd = dst[nxt0 * 128 + row]; }

    int cur = 0;
    for (int tile = t0; tile < nTiles; tile += stride) {
        int nxt = tile + stride;
        if (nxt < nTiles) {
            gather(nxt, cur ^ 1, ps, pd);
            CP_COMMIT();
            int nn2 = nxt + stride;
            if (nn2 < nTiles) { ps = src[nn2 * 128 + row]; pd = dst[nn2 * 128 + row]; }
            CP_WAIT(1);
        } else {
            CP_WAIT(0);
        }
        __syncthreads();   // buf[cur] + sdst[cur] visible to all

        // ---- MMA mainloop on Abuf[cur] ----
        float acc[2][NT][4];
        #pragma unroll
        for (int mi = 0; mi < 2; mi++)
            #pragma unroll
            for (int t = 0; t < NT; t++)
                #pragma unroll
                for (int j = 0; j < 4; j++) acc[mi][t][j] = 0.0f;

        const float* A0 = Abuf + cur * A_F32;
        for (int kc = 0; kc < KC8; kc++) {
            uint2 b[NT];
            #pragma unroll
            for (int t = 0; t < NT; t++)
                b[t] = *(const uint2*)&Wp[(((wn * NT + t) * KC8 + kc) * 32 + lane) * 2];
            #pragma unroll
            for (int mi = 0; mi < 2; mi++) {
                const float* ar = A0 + (wm * 32 + mi * 16 + g) * KP + kc * 8 + tg;
                uint32_t a[4];
                a[0] = f2tf32(ar[0]);
                a[1] = f2tf32(ar[8 * KP]);
                a[2] = f2tf32(ar[4]);
                a[3] = f2tf32(ar[8 * KP + 4]);
                #pragma unroll
                for (int t = 0; t < NT; t++)
                    mma_tf32(acc[mi][t], a, (const uint32_t*)&b[t]);
            }
        }

        // ---- epilogue: bias + relu + atomic scatter (zero-skip) ----
        #pragma unroll
        for (int mi = 0; mi < 2; mi++) {
            int r0 = wm * 32 + mi * 16 + g;
            float* row0 = agg + (size_t)sdst[cur * 128 + r0] * F + col_off;
            float* row1 = agg + (size_t)sdst[cur * 128 + r0 + 8] * F + col_off;
            #pragma unroll
            for (int t = 0; t < NT; t++) {
                int n = wn * (FK / 2) + t * 8 + tg * 2;
                float v0 = acc[mi][t][0] + br[t][0];
                float v1 = acc[mi][t][1] + br[t][1];
                float v2 = acc[mi][t][2] + br[t][0];
                float v3 = acc[mi][t][3] + br[t][1];
                if (v0 > 0.0f) atomicAdd(&row0[n], v0);
                if (v1 > 0.0f) atomicAdd(&row0[n + 1], v1);
                if (v2 > 0.0f) atomicAdd(&row1[n], v2);
                if (v3 > 0.0f) atomicAdd(&row1[n + 1], v3);
            }
        }
        __syncthreads();   // all reads of buf[cur]/sdst[cur] done before reuse
        cur ^= 1;
    }
}

// ---------------- node kernel (FFMA f32x2) ----------------
template <int FIN, int F>
__global__ __launch_bounds__(256) void node_kernel(
    const float* __restrict__ xin, const float* __restrict__ agg,
    const float* __restrict__ Ws, const float* __restrict__ bs,
    const float* __restrict__ Wc, const float* __restrict__ bc,
    const int* __restrict__ gid, const float* __restrict__ deg,
    const float* __restrict__ gcnt,
    float* __restrict__ fout, float* __restrict__ score)
{
    constexpr int P = F / 64;
    extern __shared__ float smemf[];
    float* Ws_s = smemf;
    float* Wc_s = Ws_s + FIN * F;
    float* in_s = Wc_s + F;

    const int tid = threadIdx.x;
    const int w = tid >> 5, lane = tid & 31;

    for (int i = tid; i < FIN * F; i += 256) Ws_s[i] = Ws[i];
    for (int i = tid; i < F; i += 256) Wc_s[i] = Wc[i];
    float bsr[P][2];
    #pragma unroll
    for (int p = 0; p < P; p++) {
        bsr[p][0] = bs[p * 64 + lane * 2];
        bsr[p][1] = bs[p * 64 + lane * 2 + 1];
    }
    const float bcv = bc[0];
    __syncthreads();

    const int nTiles = (NN + 31) / 32;
    for (int tile = blockIdx.x; tile < nTiles; tile += gridDim.x) {
        const int base = tile * 32;
        __syncthreads();
        for (int i = tid; i < 32 * (FIN / 4); i += 256) {
            int nl = i / (FIN / 4);
            int k4 = (i % (FIN / 4)) * 4;
            int n = base + nl;
            float4 v = make_float4(0.f, 0.f, 0.f, 0.f);
            if (n < NN) v = *(const float4*)&xin[(size_t)n * FIN + k4];
            *(float4*)&in_s[nl * FIN + k4] = v;
        }
        __syncthreads();

        unsigned long long acc[4][P];
        #pragma unroll
        for (int e = 0; e < 4; e++)
            #pragma unroll
            for (int p = 0; p < P; p++) acc[e][p] = 0ull;

        const unsigned long long* Ws2 = (const unsigned long long*)Ws_s;
        const float* in0 = &in_s[(w * 4) * FIN];

        for (int k4 = 0; k4 < FIN; k4 += 4) {
            float4 vv[4];
            #pragma unroll
            for (int e = 0; e < 4; e++)
                vv[e] = *(const float4*)&in0[e * FIN + k4];
            #pragma unroll
            for (int kk = 0; kk < 4; kk++) {
                const int k = k4 + kk;
                unsigned long long dup[4];
                #pragma unroll
                for (int e = 0; e < 4; e++) {
                    float v = (kk == 0) ? vv[e].x : (kk == 1) ? vv[e].y
                             : (kk == 2) ? vv[e].z : vv[e].w;
                    DUP2(dup[e], v);
                }
                #pragma unroll
                for (int p = 0; p < P; p++) {
                    unsigned long long w2 = Ws2[k * (F / 2) + p * 32 + lane];
                    #pragma unroll
                    for (int e = 0; e < 4; e++) FMA2(acc[e][p], dup[e], w2, acc[e][p]);
                }
            }
        }

        #pragma unroll
        for (int e = 0; e < 4; e++) {
            int n = base + w * 4 + e;
            if (n >= NN) continue;
            float inv = 1.0f / fmaxf(deg[n], 1.0f);
            const float* arow = agg + (size_t)n * F;
            float* frow = fout + (size_t)n * F;
            float cpart = 0.0f;
            #pragma unroll
            for (int p = 0; p < P; p++) {
                int c0 = p * 64 + lane * 2;
                float2 av = *(const float2*)&arow[c0];
                float lo = fmaxf(av.x * inv + __uint_as_float((unsigned)acc[e][p]) + bsr[p][0], 0.0f);
                float hi = fmaxf(av.y * inv + __uint_as_float((unsigned)(acc[e][p] >> 32)) + bsr[p][1], 0.0f);
                float2 ov; ov.x = lo; ov.y = hi;
                *(float2*)&frow[c0] = ov;
                cpart += lo * Wc_s[c0] + hi * Wc_s[c0 + 1];
            }
            #pragma unroll
            for (int off = 16; off; off >>= 1)
                cpart += __shfl_xor_sync(0xFFFFFFFFu, cpart, off);
            if (lane == 0) {
                int gg = gid[n];
                atomicAdd(&score[gg], (cpart + bcv) / fmaxf(gcnt[gg], 1.0f));
            }
        }
    }
}

// ---------------- host side ----------------
template <typename Kern>
static int grid_for(Kern k, int smem_bytes, int tiles, int nsm, int block) {
    cudaFuncSetAttribute(k, cudaFuncAttributeMaxDynamicSharedMemorySize, smem_bytes);
    int occ = 1;
    cudaOccupancyMaxActiveBlocksPerMultiprocessor(&occ, k, block, smem_bytes);
    if (occ < 1) occ = 1;
    int g = nsm * occ;
    if (g > tiles) g = tiles;
    return g;
}

template <int FIN, int K, int F, int FK>
static void launch_edge(const float* xin, const float* efeat, const int* src, const int* dst,
                        const float* Wm, const float* bm, float* agg, int col_off, int nsm)
{
    constexpr int KP = K + 4;
    const int smem = K * FK * 4 + 2 * 128 * KP * 4 + 2 * 128 * 4;
    int g = grid_for(edge_mma_kernel<FIN, K, F, FK>, smem, EE / 128, nsm, 256);
    edge_mma_kernel<FIN, K, F, FK><<<g, 256, smem>>>(xin, efeat, src, dst, Wm, bm, agg, col_off);
}

template <int FIN, int F>
static void launch_node(const float* xin, const float* agg, const float* const* Wl,
                        const int* gid, const float* deg, const float* gcnt,
                        float* fout, float* score, int nsm)
{
    const int smem_n = (FIN * F + F + 32 * FIN) * 4;
    int gn = grid_for(node_kernel<FIN, F>, smem_n, (NN + 31) / 32, nsm, 256);
    node_kernel<FIN, F><<<gn, 256, smem_n>>>(xin, agg, Wl[2], Wl[3], Wl[4], Wl[5],
                                             gid, deg, gcnt, fout, score);
}

extern "C" void kernel_launch(void* const* d_in, const int* in_sizes, int n_in,
                              void* d_out, int out_size)
{
    const float* x   = (const float*)d_in[0];
    const float* e   = (const float*)d_in[1];
    const int*   src = (const int*)d_in[2];
    const int*   dst = (const int*)d_in[3];
    const int*   gid = (const int*)d_in[4];
    const float* W[4][6];
    for (int l = 0; l < 4; l++)
        for (int j = 0; j < 6; j++)
            W[l][j] = (const float*)d_in[5 + l * 6 + j];
    float* score = (float*)d_out;

    float *bufA, *bufB, *agg, *deg, *gcnt;
    cudaGetSymbolAddress((void**)&bufA, g_bufA);
    cudaGetSymbolAddress((void**)&bufB, g_bufB);
    cudaGetSymbolAddress((void**)&agg, g_agg);
    cudaGetSymbolAddress((void**)&deg, g_deg);
    cudaGetSymbolAddress((void**)&gcnt, g_gcnt);

    int nsm = 148;
    cudaDeviceGetAttribute(&nsm, cudaDevAttrMultiProcessorCount, 0);

    cudaMemsetAsync(deg, 0, NN * sizeof(float));
    cudaMemsetAsync(gcnt, 0, GG * sizeof(float));
    cudaMemsetAsync(score, 0, GG * sizeof(float));
    count_kernel<<<(EE + 255) / 256, 256>>>(dst, gid, deg, gcnt);

    // layer 0: K=48, F=64
    cudaMemsetAsync(agg, 0, (size_t)NN * 64 * sizeof(float));
    launch_edge<32, 48, 64, 64>(x, e, src, dst, W[0][0], W[0][1], agg, 0, nsm);
    launch_node<32, 64>(x, agg, W[0], gid, deg, gcnt, bufA, score, nsm);

    // layer 1: K=80, F=128
    cudaMemsetAsync(agg, 0, (size_t)NN * 128 * sizeof(float));
    launch_edge<64, 80, 128, 128>(bufA, e, src, dst, W[1][0], W[1][1], agg, 0, nsm);
    launch_node<64, 128>(bufA, agg, W[1], gid, deg, gcnt, bufB, score, nsm);

    // layer 2: K=144, F=128
    cudaMemsetAsync(agg, 0, (size_t)NN * 128 * sizeof(float));
    launch_edge<128, 144, 128, 128>(bufB, e, src, dst, W[2][0], W[2][1], agg, 0, nsm);
    launch_node<128, 128>(bufB, agg, W[2], gid, deg, gcnt, bufA, score, nsm);

    // layer 3: K=144, F=256 (two FK=128 halves)
    cudaMemsetAsync(agg, 0, (size_t)NN * 256 * sizeof(float));
    launch_edge<128, 144, 256, 128>(bufA, e, src, dst, W[3][0], W[3][1], agg, 0, nsm);
    launch_edge<128, 144, 256, 128>(bufA, e, src, dst, W[3][0], W[3][1], agg, 128, nsm);
    launch_node<128, 256>(bufA, agg, W[3], gid, deg, gcnt, bufB, score, nsm);
}

// round 8
// speedup vs baseline: 2.4346x; 1.0558x over previous
#include <cuda_runtime.h>
#include <cstdint>

#define NN 50000
#define EE 800000
#define GG 512
#define EFD 16

// ---------------- scratch (no allocations allowed) ----------------
__device__ float g_bufA[NN * 256];
__device__ float g_bufB[NN * 256];
__device__ float g_agg[NN * 256];
__device__ float g_deg[NN];
__device__ float g_gcnt[GG];

// ---------------- helpers ----------------
__device__ __forceinline__ uint32_t f2tf32(float x) {
    uint32_t r;
    asm("cvt.rna.tf32.f32 %0, %1;" : "=r"(r) : "f"(x));
    return r;
}
__device__ __forceinline__ uint32_t smem_u32(const void* p) {
    uint32_t a;
    asm("{ .reg .u64 t; cvta.to.shared.u64 t, %1; cvt.u32.u64 %0, t; }" : "=r"(a) : "l"(p));
    return a;
}
__device__ __forceinline__ void cp16(uint32_t saddr, const void* gaddr) {
    asm volatile("cp.async.ca.shared.global [%0], [%1], 16;" :: "r"(saddr), "l"(gaddr) : "memory");
}
#define CP_COMMIT() asm volatile("cp.async.commit_group;" ::: "memory")
#define CP_WAIT(n)  asm volatile("cp.async.wait_group %0;" :: "n"(n) : "memory")

// D += A(16x8,row) * B(8x8,col), tf32 inputs, f32 accum
__device__ __forceinline__ void mma_tf32(float* d, const uint32_t* a, const uint32_t* b) {
    asm volatile(
        "mma.sync.aligned.m16n8k8.row.col.f32.tf32.tf32.f32 "
        "{%0,%1,%2,%3}, {%4,%5,%6,%7}, {%8,%9}, {%0,%1,%2,%3};"
        : "+f"(d[0]), "+f"(d[1]), "+f"(d[2]), "+f"(d[3])
        : "r"(a[0]), "r"(a[1]), "r"(a[2]), "r"(a[3]), "r"(b[0]), "r"(b[1]));
}

// packed f32x2 FMA (plain PTX, sm_103 ok)
#define FMA2(d, a, b, c) \
    asm("fma.rn.f32x2 %0, %1, %2, %3;" : "=l"(d) : "l"(a), "l"(b), "l"(c))
#define DUP2(d, s) \
    asm("mov.b64 %0, {%1, %1};" : "=l"(d) : "r"(__float_as_uint(s)))

__global__ void count_kernel(const int* __restrict__ dst, const int* __restrict__ gid,
                             float* __restrict__ deg, float* __restrict__ gcnt) {
    int i = blockIdx.x * blockDim.x + threadIdx.x;
    if (i < EE) atomicAdd(&deg[dst[i]], 1.0f);
    if (i < NN) atomicAdd(&gcnt[gid[i]], 1.0f);
}

// ---------------- pipelined tensor-core edge kernel ----------------
// agg[dst] += relu(concat(x[src], e) @ Wm[:, col_off:+FK] + bm).
// TILE edges per iteration; block = 256 threads = 8 warps (4 row-slabs x 2 col-halves).
// Single A buffer: gather of tile t+1 is issued between mainloop(t) and epilogue(t),
// overlapping cp.async with the atomic epilogue. 2 blocks/SM co-schedule phases.
template <int FIN, int K, int F, int FK, int TILE>
__global__ __launch_bounds__(256, 2)
void edge_mma_kernel(const float* __restrict__ xin, const float* __restrict__ efeat,
                     const int* __restrict__ src, const int* __restrict__ dst,
                     const float* __restrict__ Wm, const float* __restrict__ bm,
                     float* __restrict__ agg, int col_off)
{
    constexpr int KP = K + 4;            // KP % 32 == 20 -> conflict-free fragment LDS
    constexpr int KC8 = K / 8;
    constexpr int NT = FK / 16;          // n8 tiles per warp
    constexpr int MI = TILE / 64;        // m16 tiles per warp slab
    constexpr int TPR = 256 / TILE;      // gather threads per edge row
    constexpr int W_U32 = K * FK;
    constexpr int A_F32 = TILE * KP;

    extern __shared__ char smem[];
    uint32_t* Wp = (uint32_t*)smem;                                      // W_U32
    float* Abuf = (float*)(smem + (size_t)W_U32 * 4);                    // A_F32
    int* sdst = (int*)(smem + (size_t)W_U32 * 4 + (size_t)A_F32 * 4);    // 2 * TILE

    const int tid = threadIdx.x;
    const int w = tid >> 5, lane = tid & 31;
    const int wm = w >> 1, wn = w & 1;           // 4 row-slabs x 2 col-halves
    const int g = lane >> 2, tg = lane & 3;
    const int row = tid / TPR, h = tid % TPR;    // gather mapping
    const uint32_t sbA = smem_u32(Abuf);

    // stage weights in B-fragment order (tf32)
    for (int i = tid; i < K * FK; i += 256) {
        int k = i / FK, n = i % FK;
        uint32_t val = f2tf32(Wm[k * F + col_off + n]);
        int T = n >> 3, kc = k >> 3;
        Wp[((T * KC8 + kc) * 32 + (n & 7) * 4 + (k & 3)) * 2 + ((k >> 2) & 1)] = val;
    }
    float br[NT][2];
    #pragma unroll
    for (int t = 0; t < NT; t++) {
        int n = wn * (FK / 2) + t * 8 + tg * 2;
        br[t][0] = bm[col_off + n];
        br[t][1] = bm[col_off + n + 1];
    }

    const int nTiles = EE / TILE;  // exact for TILE in {64,128}
    const int stride = gridDim.x;

    // issue cp.async gather for tile -> A buffer; srow/sd prefetched
    auto gather = [&](int tile, int par, int srow, int sd) {
        int base = tile * TILE;
        if (h == 0) sdst[par * TILE + row] = sd;
        uint32_t arow = sbA + (uint32_t)(row * KP) * 4;
        const char* xr = (const char*)(xin + (size_t)srow * FIN);
        #pragma unroll
        for (int c = h; c < FIN / 4; c += TPR) cp16(arow + c * 16, xr + c * 16);
        const char* er = (const char*)(efeat + (size_t)(base + row) * EFD);
        #pragma unroll
        for (int c = h; c < EFD / 4; c += TPR) cp16(arow + FIN * 4 + c * 16, er + c * 16);
    };

    // preamble
    int t0 = blockIdx.x;
    int ps = src[t0 * TILE + row];
    int pd = dst[t0 * TILE + row];
    gather(t0, 0, ps, pd);
    CP_COMMIT();
    int nxt0 = t0 + stride;
    if (nxt0 < nTiles) { ps = src[nxt0 * TILE + row]; pd = dst[nxt0 * TILE + row]; }

    int par = 0;
    for (int tile = t0; tile < nTiles; tile += stride) {
        CP_WAIT(0);
        __syncthreads();   // A + sdst[par] visible to all

        // ---- MMA mainloop on Abuf ----
        float acc[MI][NT][4];
        #pragma unroll
        for (int mi = 0; mi < MI; mi++)
            #pragma unroll
            for (int t = 0; t < NT; t++)
                #pragma unroll
                for (int j = 0; j < 4; j++) acc[mi][t][j] = 0.0f;

        for (int kc = 0; kc < KC8; kc++) {
            uint2 b[NT];
            #pragma unroll
            for (int t = 0; t < NT; t++)
                b[t] = *(const uint2*)&Wp[(((wn * NT + t) * KC8 + kc) * 32 + lane) * 2];
            #pragma unroll
            for (int mi = 0; mi < MI; mi++) {
                const float* ar = Abuf + (wm * (TILE / 4) + mi * 16 + g) * KP + kc * 8 + tg;
                uint32_t a[4];
                a[0] = f2tf32(ar[0]);
                a[1] = f2tf32(ar[8 * KP]);
                a[2] = f2tf32(ar[4]);
                a[3] = f2tf32(ar[8 * KP + 4]);
                #pragma unroll
                for (int t = 0; t < NT; t++)
                    mma_tf32(acc[mi][t], a, (const uint32_t*)&b[t]);
            }
        }
        __syncthreads();   // all warps finished reading Abuf

        // ---- issue next tile's gather now; overlaps with the atomic epilogue ----
        int nxt = tile + stride;
        if (nxt < nTiles) {
            gather(nxt, par ^ 1, ps, pd);
            CP_COMMIT();
            int nn2 = nxt + stride;
            if (nn2 < nTiles) { ps = src[nn2 * TILE + row]; pd = dst[nn2 * TILE + row]; }
        }

        // ---- epilogue: bias + relu + atomic scatter (zero-skip) ----
        #pragma unroll
        for (int mi = 0; mi < MI; mi++) {
            int r0 = wm * (TILE / 4) + mi * 16 + g;
            float* row0 = agg + (size_t)sdst[par * TILE + r0] * F + col_off;
            float* row1 = agg + (size_t)sdst[par * TILE + r0 + 8] * F + col_off;
            #pragma unroll
            for (int t = 0; t < NT; t++) {
                int n = wn * (FK / 2) + t * 8 + tg * 2;
                float v0 = acc[mi][t][0] + br[t][0];
                float v1 = acc[mi][t][1] + br[t][1];
                float v2 = acc[mi][t][2] + br[t][0];
                float v3 = acc[mi][t][3] + br[t][1];
                if (v0 > 0.0f) atomicAdd(&row0[n], v0);
                if (v1 > 0.0f) atomicAdd(&row0[n + 1], v1);
                if (v2 > 0.0f) atomicAdd(&row1[n], v2);
                if (v3 > 0.0f) atomicAdd(&row1[n + 1], v3);
            }
        }
        par ^= 1;
    }
}

// ---------------- node kernel (FFMA f32x2) ----------------
template <int FIN, int F>
__global__ __launch_bounds__(256) void node_kernel(
    const float* __restrict__ xin, const float* __restrict__ agg,
    const float* __restrict__ Ws, const float* __restrict__ bs,
    const float* __restrict__ Wc, const float* __restrict__ bc,
    const int* __restrict__ gid, const float* __restrict__ deg,
    const float* __restrict__ gcnt,
    float* __restrict__ fout, float* __restrict__ score)
{
    constexpr int P = F / 64;
    extern __shared__ float smemf[];
    float* Ws_s = smemf;
    float* Wc_s = Ws_s + FIN * F;
    float* in_s = Wc_s + F;

    const int tid = threadIdx.x;
    const int w = tid >> 5, lane = tid & 31;

    for (int i = tid; i < FIN * F; i += 256) Ws_s[i] = Ws[i];
    for (int i = tid; i < F; i += 256) Wc_s[i] = Wc[i];
    float bsr[P][2];
    #pragma unroll
    for (int p = 0; p < P; p++) {
        bsr[p][0] = bs[p * 64 + lane * 2];
        bsr[p][1] = bs[p * 64 + lane * 2 + 1];
    }
    const float bcv = bc[0];
    __syncthreads();

    const int nTiles = (NN + 31) / 32;
    for (int tile = blockIdx.x; tile < nTiles; tile += gridDim.x) {
        const int base = tile * 32;
        __syncthreads();
        for (int i = tid; i < 32 * (FIN / 4); i += 256) {
            int nl = i / (FIN / 4);
            int k4 = (i % (FIN / 4)) * 4;
            int n = base + nl;
            float4 v = make_float4(0.f, 0.f, 0.f, 0.f);
            if (n < NN) v = *(const float4*)&xin[(size_t)n * FIN + k4];
            *(float4*)&in_s[nl * FIN + k4] = v;
        }
        __syncthreads();

        unsigned long long acc[4][P];
        #pragma unroll
        for (int e = 0; e < 4; e++)
            #pragma unroll
            for (int p = 0; p < P; p++) acc[e][p] = 0ull;

        const unsigned long long* Ws2 = (const unsigned long long*)Ws_s;
        const float* in0 = &in_s[(w * 4) * FIN];

        for (int k4 = 0; k4 < FIN; k4 += 4) {
            float4 vv[4];
            #pragma unroll
            for (int e = 0; e < 4; e++)
                vv[e] = *(const float4*)&in0[e * FIN + k4];
            #pragma unroll
            for (int kk = 0; kk < 4; kk++) {
                const int k = k4 + kk;
                unsigned long long dup[4];
                #pragma unroll
                for (int e = 0; e < 4; e++) {
                    float v = (kk == 0) ? vv[e].x : (kk == 1) ? vv[e].y
                             : (kk == 2) ? vv[e].z : vv[e].w;
                    DUP2(dup[e], v);
                }
                #pragma unroll
                for (int p = 0; p < P; p++) {
                    unsigned long long w2 = Ws2[k * (F / 2) + p * 32 + lane];
                    #pragma unroll
                    for (int e = 0; e < 4; e++) FMA2(acc[e][p], dup[e], w2, acc[e][p]);
                }
            }
        }

        #pragma unroll
        for (int e = 0; e < 4; e++) {
            int n = base + w * 4 + e;
            if (n >= NN) continue;
            float inv = 1.0f / fmaxf(deg[n], 1.0f);
            const float* arow = agg + (size_t)n * F;
            float* frow = fout + (size_t)n * F;
            float cpart = 0.0f;
            #pragma unroll
            for (int p = 0; p < P; p++) {
                int c0 = p * 64 + lane * 2;
                float2 av = *(const float2*)&arow[c0];
                float lo = fmaxf(av.x * inv + __uint_as_float((unsigned)acc[e][p]) + bsr[p][0], 0.0f);
                float hi = fmaxf(av.y * inv + __uint_as_float((unsigned)(acc[e][p] >> 32)) + bsr[p][1], 0.0f);
                float2 ov; ov.x = lo; ov.y = hi;
                *(float2*)&frow[c0] = ov;
                cpart += lo * Wc_s[c0] + hi * Wc_s[c0 + 1];
            }
            #pragma unroll
            for (int off = 16; off; off >>= 1)
                cpart += __shfl_xor_sync(0xFFFFFFFFu, cpart, off);
            if (lane == 0) {
                int gg = gid[n];
                atomicAdd(&score[gg], (cpart + bcv) / fmaxf(gcnt[gg], 1.0f));
            }
        }
    }
}

// ---------------- host side ----------------
template <typename Kern>
static int grid_for(Kern k, int smem_bytes, int tiles, int nsm, int block) {
    cudaFuncSetAttribute(k, cudaFuncAttributeMaxDynamicSharedMemorySize, smem_bytes);
    int occ = 1;
    cudaOccupancyMaxActiveBlocksPerMultiprocessor(&occ, k, block, smem_bytes);
    if (occ < 1) occ = 1;
    int g = nsm * occ;
    if (g > tiles) g = tiles;
    return g;
}

template <int FIN, int K, int F, int FK, int TILE>
static void launch_edge(const float* xin, const float* efeat, const int* src, const int* dst,
                        const float* Wm, const float* bm, float* agg, int col_off, int nsm)
{
    constexpr int KP = K + 4;
    const int smem = K * FK * 4 + TILE * KP * 4 + 2 * TILE * 4;
    int g = grid_for(edge_mma_kernel<FIN, K, F, FK, TILE>, smem, EE / TILE, nsm, 256);
    edge_mma_kernel<FIN, K, F, FK, TILE><<<g, 256, smem>>>(xin, efeat, src, dst, Wm, bm, agg, col_off);
}

template <int FIN, int F>
static void launch_node(const float* xin, const float* agg, const float* const* Wl,
                        const int* gid, const float* deg, const float* gcnt,
                        float* fout, float* score, int nsm)
{
    const int smem_n = (FIN * F + F + 32 * FIN) * 4;
    int gn = grid_for(node_kernel<FIN, F>, smem_n, (NN + 31) / 32, nsm, 256);
    node_kernel<FIN, F><<<gn, 256, smem_n>>>(xin, agg, Wl[2], Wl[3], Wl[4], Wl[5],
                                             gid, deg, gcnt, fout, score);
}

extern "C" void kernel_launch(void* const* d_in, const int* in_sizes, int n_in,
                              void* d_out, int out_size)
{
    const float* x   = (const float*)d_in[0];
    const float* e   = (const float*)d_in[1];
    const int*   src = (const int*)d_in[2];
    const int*   dst = (const int*)d_in[3];
    const int*   gid = (const int*)d_in[4];
    const float* W[4][6];
    for (int l = 0; l < 4; l++)
        for (int j = 0; j < 6; j++)
            W[l][j] = (const float*)d_in[5 + l * 6 + j];
    float* score = (float*)d_out;

    float *bufA, *bufB, *agg, *deg, *gcnt;
    cudaGetSymbolAddress((void**)&bufA, g_bufA);
    cudaGetSymbolAddress((void**)&bufB, g_bufB);
    cudaGetSymbolAddress((void**)&agg, g_agg);
    cudaGetSymbolAddress((void**)&deg, g_deg);
    cudaGetSymbolAddress((void**)&gcnt, g_gcnt);

    int nsm = 148;
    cudaDeviceGetAttribute(&nsm, cudaDevAttrMultiProcessorCount, 0);

    cudaMemsetAsync(deg, 0, NN * sizeof(float));
    cudaMemsetAsync(gcnt, 0, GG * sizeof(float));
    cudaMemsetAsync(score, 0, GG * sizeof(float));
    count_kernel<<<(EE + 255) / 256, 256>>>(dst, gid, deg, gcnt);

    // layer 0: K=48, F=64, TILE=128
    cudaMemsetAsync(agg, 0, (size_t)NN * 64 * sizeof(float));
    launch_edge<32, 48, 64, 64, 128>(x, e, src, dst, W[0][0], W[0][1], agg, 0, nsm);
    launch_node<32, 64>(x, agg, W[0], gid, deg, gcnt, bufA, score, nsm);

    // layer 1: K=80, F=128, TILE=128
    cudaMemsetAsync(agg, 0, (size_t)NN * 128 * sizeof(float));
    launch_edge<64, 80, 128, 128, 128>(bufA, e, src, dst, W[1][0], W[1][1], agg, 0, nsm);
    launch_node<64, 128>(bufA, agg, W[1], gid, deg, gcnt, bufB, score, nsm);

    // layer 2: K=144, F=128, TILE=64 (2 blocks/SM)
    cudaMemsetAsync(agg, 0, (size_t)NN * 128 * sizeof(float));
    launch_edge<128, 144, 128, 128, 64>(bufB, e, src, dst, W[2][0], W[2][1], agg, 0, nsm);
    launch_node<128, 128>(bufB, agg, W[2], gid, deg, gcnt, bufA, score, nsm);

    // layer 3: K=144, F=256, TILE=64 (two FK=128 halves)
    cudaMemsetAsync(agg, 0, (size_t)NN * 256 * sizeof(float));
    launch_edge<128, 144, 256, 128, 64>(bufA, e, src, dst, W[3][0], W[3][1], agg, 0, nsm);
    launch_edge<128, 144, 256, 128, 64>(bufA, e, src, dst, W[3][0], W[3][1], agg, 128, nsm);
    launch_node<128, 256>(bufA, agg, W[3], gid, deg, gcnt, bufB, score, nsm);
}

// round 9
// speedup vs baseline: 2.6916x; 1.1056x over previous
#include <cuda_runtime.h>
#include <cstdint>

#define NN 50000
#define EE 800000
#define GG 512
#define EFD 16

// ---------------- scratch (no allocations allowed) ----------------
__device__ float g_bufA[NN * 256];
__device__ float g_bufB[NN * 256];
__device__ float g_agg[NN * 256];
__device__ float g_u[NN * 256];
__device__ float g_deg[NN];
__device__ float g_gcnt[GG];

// ---------------- helpers ----------------
__device__ __forceinline__ uint32_t f2tf32(float x) {
    uint32_t r;
    asm("cvt.rna.tf32.f32 %0, %1;" : "=r"(r) : "f"(x));
    return r;
}
__device__ __forceinline__ uint32_t smem_u32(const void* p) {
    uint32_t a;
    asm("{ .reg .u64 t; cvta.to.shared.u64 t, %1; cvt.u32.u64 %0, t; }" : "=r"(a) : "l"(p));
    return a;
}
__device__ __forceinline__ void cp16(uint32_t saddr, const void* gaddr) {
    asm volatile("cp.async.ca.shared.global [%0], [%1], 16;" :: "r"(saddr), "l"(gaddr) : "memory");
}
#define CP_COMMIT() asm volatile("cp.async.commit_group;" ::: "memory")
#define CP_WAIT(n)  asm volatile("cp.async.wait_group %0;" :: "n"(n) : "memory")

// D += A(16x8,row) * B(8x8,col), tf32 inputs, f32 accum
__device__ __forceinline__ void mma_tf32(float* d, const uint32_t* a, const uint32_t* b) {
    asm volatile(
        "mma.sync.aligned.m16n8k8.row.col.f32.tf32.tf32.f32 "
        "{%0,%1,%2,%3}, {%4,%5,%6,%7}, {%8,%9}, {%0,%1,%2,%3};"
        : "+f"(d[0]), "+f"(d[1]), "+f"(d[2]), "+f"(d[3])
        : "r"(a[0]), "r"(a[1]), "r"(a[2]), "r"(a[3]), "r"(b[0]), "r"(b[1]));
}

// packed f32x2 FMA
#define FMA2(d, a, b, c) \
    asm("fma.rn.f32x2 %0, %1, %2, %3;" : "=l"(d) : "l"(a), "l"(b), "l"(c))
#define DUP2(d, s) \
    asm("mov.b64 %0, {%1, %1};" : "=l"(d) : "r"(__float_as_uint(s)))

__global__ void count_kernel(const int* __restrict__ dst, const int* __restrict__ gid,
                             float* __restrict__ deg, float* __restrict__ gcnt) {
    int i = blockIdx.x * blockDim.x + threadIdx.x;
    if (i < EE) atomicAdd(&deg[dst[i]], 1.0f);
    if (i < NN) atomicAdd(&gcnt[gid[i]], 1.0f);
}

// ---------------- dense u-kernel: u[:, col_off:+FK] = feat @ Wm[0:FIN, col_off:+FK] ----------------
// Dense tf32 MMA over 50k node rows. Block=256 (8 warps, 4x2). No bias, no relu.
template <int FIN, int F, int FK, int TILE>
__global__ __launch_bounds__(256)
void u_kernel(const float* __restrict__ xin, const float* __restrict__ Wm,
              float* __restrict__ uout, int col_off)
{
    constexpr int KP = FIN + 4;
    constexpr int KC8 = FIN / 8;
    constexpr int NT = FK / 16;
    constexpr int MI = TILE / 64;
    constexpr int TPR = 256 / TILE;
    constexpr int W_U32 = FIN * FK;

    extern __shared__ char smem[];
    uint32_t* Wp = (uint32_t*)smem;                     // W_U32
    float* Abuf = (float*)(smem + (size_t)W_U32 * 4);   // TILE*KP

    const int tid = threadIdx.x;
    const int w = tid >> 5, lane = tid & 31;
    const int wm = w >> 1, wn = w & 1;
    const int g = lane >> 2, tg = lane & 3;
    const int row = tid / TPR, h = tid % TPR;
    const uint32_t sbA = smem_u32(Abuf);

    for (int i = tid; i < FIN * FK; i += 256) {
        int k = i / FK, n = i % FK;
        uint32_t val = f2tf32(Wm[k * F + col_off + n]);
        int T = n >> 3, kc = k >> 3;
        Wp[((T * KC8 + kc) * 32 + (n & 7) * 4 + (k & 3)) * 2 + ((k >> 2) & 1)] = val;
    }

    const int nTiles = (NN + TILE - 1) / TILE;
    const int stride = gridDim.x;

    auto gather = [&](int tile) {
        int grow = tile * TILE + row;
        if (grow >= NN) grow = NN - 1;
        uint32_t arow = sbA + (uint32_t)(row * KP) * 4;
        const char* xr = (const char*)(xin + (size_t)grow * FIN);
        #pragma unroll
        for (int c = h; c < FIN / 4; c += TPR) cp16(arow + c * 16, xr + c * 16);
    };

    int t0 = blockIdx.x;
    gather(t0);
    CP_COMMIT();

    for (int tile = t0; tile < nTiles; tile += stride) {
        CP_WAIT(0);
        __syncthreads();

        float acc[MI][NT][4];
        #pragma unroll
        for (int mi = 0; mi < MI; mi++)
            #pragma unroll
            for (int t = 0; t < NT; t++)
                #pragma unroll
                for (int j = 0; j < 4; j++) acc[mi][t][j] = 0.0f;

        for (int kc = 0; kc < KC8; kc++) {
            uint2 b[NT];
            #pragma unroll
            for (int t = 0; t < NT; t++)
                b[t] = *(const uint2*)&Wp[(((wn * NT + t) * KC8 + kc) * 32 + lane) * 2];
            #pragma unroll
            for (int mi = 0; mi < MI; mi++) {
                const float* ar = Abuf + (wm * (TILE / 4) + mi * 16 + g) * KP + kc * 8 + tg;
                uint32_t a[4];
                a[0] = f2tf32(ar[0]);
                a[1] = f2tf32(ar[8 * KP]);
                a[2] = f2tf32(ar[4]);
                a[3] = f2tf32(ar[8 * KP + 4]);
                #pragma unroll
                for (int t = 0; t < NT; t++)
                    mma_tf32(acc[mi][t], a, (const uint32_t*)&b[t]);
            }
        }
        __syncthreads();

        int nxt = tile + stride;
        if (nxt < nTiles) { gather(nxt); CP_COMMIT(); }

        const int base = tile * TILE;
        #pragma unroll
        for (int mi = 0; mi < MI; mi++) {
            int r0 = wm * (TILE / 4) + mi * 16 + g;
            int gr0 = base + r0, gr1 = gr0 + 8;
            #pragma unroll
            for (int t = 0; t < NT; t++) {
                int n = wn * (FK / 2) + t * 8 + tg * 2;
                if (gr0 < NN) {
                    float2 v; v.x = acc[mi][t][0]; v.y = acc[mi][t][1];
                    *(float2*)&uout[(size_t)gr0 * F + col_off + n] = v;
                }
                if (gr1 < NN) {
                    float2 v; v.x = acc[mi][t][2]; v.y = acc[mi][t][3];
                    *(float2*)&uout[(size_t)gr1 * F + col_off + n] = v;
                }
            }
        }
    }
}

// ---------------- edge kernel: agg[dst] += relu(u[src] + e @ Wme + bm) ----------------
// K=16 MMA over edge features only; gathered u rows added in the epilogue.
// TILE=128 edges; block=256 (8 warps, 4x2). Single buffer; next gather overlaps epilogue.
template <int F, int FK>
__global__ __launch_bounds__(256)
void edge_mma_kernel(const float* __restrict__ u, const float* __restrict__ efeat,
                     const int* __restrict__ src, const int* __restrict__ dst,
                     const float* __restrict__ Wme,  // = Wm + FIN*F (16 rows, stride F)
                     const float* __restrict__ bm,
                     float* __restrict__ agg, int col_off)
{
    constexpr int K = EFD;               // 16
    constexpr int KP = K + 4;            // 20
    constexpr int KC8 = K / 8;           // 2
    constexpr int NT = FK / 16;
    constexpr int TILE = 128;
    constexpr int MI = 2;
    constexpr int US = FK + 8;           // u smem stride (conflict-free LDS.64)
    constexpr int W_U32 = K * FK;
    constexpr int A_F32 = TILE * KP;
    constexpr int U_F32 = TILE * US;

    extern __shared__ char smem[];
    uint32_t* Wp = (uint32_t*)smem;                                     // W_U32
    float* Abuf = (float*)(smem + (size_t)W_U32 * 4);                   // A_F32
    float* Ubuf = Abuf + A_F32;                                         // U_F32
    int* sdst = (int*)(Ubuf + U_F32);                                   // 2*TILE

    const int tid = threadIdx.x;
    const int w = tid >> 5, lane = tid & 31;
    const int wm = w >> 1, wn = w & 1;
    const int g = lane >> 2, tg = lane & 3;
    const int row = tid >> 1, h = tid & 1;   // 2 gather threads per edge row
    const uint32_t sbA = smem_u32(Abuf);
    const uint32_t sbU = smem_u32(Ubuf);

    for (int i = tid; i < K * FK; i += 256) {
        int k = i / FK, n = i % FK;
        uint32_t val = f2tf32(Wme[k * F + col_off + n]);
        int T = n >> 3, kc = k >> 3;
        Wp[((T * KC8 + kc) * 32 + (n & 7) * 4 + (k & 3)) * 2 + ((k >> 2) & 1)] = val;
    }
    float br[NT][2];
    #pragma unroll
    for (int t = 0; t < NT; t++) {
        int n = wn * (FK / 2) + t * 8 + tg * 2;
        br[t][0] = bm[col_off + n];
        br[t][1] = bm[col_off + n + 1];
    }

    const int nTiles = EE / TILE;  // 6250
    const int stride = gridDim.x;

    auto gather = [&](int tile, int par, int srow, int sd) {
        int base = tile * TILE;
        if (h == 0) sdst[par * TILE + row] = sd;
        uint32_t arow = sbA + (uint32_t)(row * KP) * 4;
        const char* er = (const char*)(efeat + (size_t)(base + row) * EFD);
        #pragma unroll
        for (int c = h; c < EFD / 4; c += 2) cp16(arow + c * 16, er + c * 16);
        uint32_t urow = sbU + (uint32_t)(row * US) * 4;
        const char* ur = (const char*)(u + (size_t)srow * F + col_off);
        #pragma unroll
        for (int c = h; c < FK / 4; c += 2) cp16(urow + c * 16, ur + c * 16);
    };

    int t0 = blockIdx.x;
    int ps = src[t0 * TILE + row];
    int pd = dst[t0 * TILE + row];
    gather(t0, 0, ps, pd);
    CP_COMMIT();
    int nxt0 = t0 + stride;
    if (nxt0 < nTiles) { ps = src[nxt0 * TILE + row]; pd = dst[nxt0 * TILE + row]; }

    int par = 0;
    for (int tile = t0; tile < nTiles; tile += stride) {
        CP_WAIT(0);
        __syncthreads();

        float acc[MI][NT][4];
        #pragma unroll
        for (int mi = 0; mi < MI; mi++)
            #pragma unroll
            for (int t = 0; t < NT; t++)
                #pragma unroll
                for (int j = 0; j < 4; j++) acc[mi][t][j] = 0.0f;

        #pragma unroll
        for (int kc = 0; kc < KC8; kc++) {
            uint2 b[NT];
            #pragma unroll
            for (int t = 0; t < NT; t++)
                b[t] = *(const uint2*)&Wp[(((wn * NT + t) * KC8 + kc) * 32 + lane) * 2];
            #pragma unroll
            for (int mi = 0; mi < MI; mi++) {
                const float* ar = Abuf + (wm * 32 + mi * 16 + g) * KP + kc * 8 + tg;
                uint32_t a[4];
                a[0] = f2tf32(ar[0]);
                a[1] = f2tf32(ar[8 * KP]);
                a[2] = f2tf32(ar[4]);
                a[3] = f2tf32(ar[8 * KP + 4]);
                #pragma unroll
                for (int t = 0; t < NT; t++)
                    mma_tf32(acc[mi][t], a, (const uint32_t*)&b[t]);
            }
        }

        // epilogue reads Ubuf/Abuf of this tile; next gather must wait for readers.
        // u additions first (LDS), then overlap gather with atomics:
        float vv[MI][NT][4];
        #pragma unroll
        for (int mi = 0; mi < MI; mi++) {
            int r0 = wm * 32 + mi * 16 + g;
            const float* ur0 = Ubuf + (size_t)r0 * US;
            #pragma unroll
            for (int t = 0; t < NT; t++) {
                int n = wn * (FK / 2) + t * 8 + tg * 2;
                float2 u0 = *(const float2*)&ur0[n];
                float2 u1 = *(const float2*)&ur0[8 * US + n];
                vv[mi][t][0] = acc[mi][t][0] + u0.x + br[t][0];
                vv[mi][t][1] = acc[mi][t][1] + u0.y + br[t][1];
                vv[mi][t][2] = acc[mi][t][2] + u1.x + br[t][0];
                vv[mi][t][3] = acc[mi][t][3] + u1.y + br[t][1];
            }
        }
        int d0[MI], d1[MI];
        #pragma unroll
        for (int mi = 0; mi < MI; mi++) {
            int r0 = wm * 32 + mi * 16 + g;
            d0[mi] = sdst[par * TILE + r0];
            d1[mi] = sdst[par * TILE + r0 + 8];
        }
        __syncthreads();   // all reads of Abuf/Ubuf/sdst done

        int nxt = tile + stride;
        if (nxt < nTiles) {
            gather(nxt, par ^ 1, ps, pd);
            CP_COMMIT();
            int nn2 = nxt + stride;
            if (nn2 < nTiles) { ps = src[nn2 * TILE + row]; pd = dst[nn2 * TILE + row]; }
        }

        // atomic scatter (zero-skip) — overlaps the in-flight cp.async
        #pragma unroll
        for (int mi = 0; mi < MI; mi++) {
            float* row0 = agg + (size_t)d0[mi] * F + col_off;
            float* row1 = agg + (size_t)d1[mi] * F + col_off;
            #pragma unroll
            for (int t = 0; t < NT; t++) {
                int n = wn * (FK / 2) + t * 8 + tg * 2;
                if (vv[mi][t][0] > 0.0f) atomicAdd(&row0[n], vv[mi][t][0]);
                if (vv[mi][t][1] > 0.0f) atomicAdd(&row0[n + 1], vv[mi][t][1]);
                if (vv[mi][t][2] > 0.0f) atomicAdd(&row1[n], vv[mi][t][2]);
                if (vv[mi][t][3] > 0.0f) atomicAdd(&row1[n + 1], vv[mi][t][3]);
            }
        }
        par ^= 1;
    }
}

// ---------------- node kernel (FFMA f32x2) ----------------
template <int FIN, int F>
__global__ __launch_bounds__(256) void node_kernel(
    const float* __restrict__ xin, const float* __restrict__ agg,
    const float* __restrict__ Ws, const float* __restrict__ bs,
    const float* __restrict__ Wc, const float* __restrict__ bc,
    const int* __restrict__ gid, const float* __restrict__ deg,
    const float* __restrict__ gcnt,
    float* __restrict__ fout, float* __restrict__ score)
{
    constexpr int P = F / 64;
    extern __shared__ float smemf[];
    float* Ws_s = smemf;
    float* Wc_s = Ws_s + FIN * F;
    float* in_s = Wc_s + F;

    const int tid = threadIdx.x;
    const int w = tid >> 5, lane = tid & 31;

    for (int i = tid; i < FIN * F; i += 256) Ws_s[i] = Ws[i];
    for (int i = tid; i < F; i += 256) Wc_s[i] = Wc[i];
    float bsr[P][2];
    #pragma unroll
    for (int p = 0; p < P; p++) {
        bsr[p][0] = bs[p * 64 + lane * 2];
        bsr[p][1] = bs[p * 64 + lane * 2 + 1];
    }
    const float bcv = bc[0];
    __syncthreads();

    const int nTiles = (NN + 31) / 32;
    for (int tile = blockIdx.x; tile < nTiles; tile += gridDim.x) {
        const int base = tile * 32;
        __syncthreads();
        for (int i = tid; i < 32 * (FIN / 4); i += 256) {
            int nl = i / (FIN / 4);
            int k4 = (i % (FIN / 4)) * 4;
            int n = base + nl;
            float4 v = make_float4(0.f, 0.f, 0.f, 0.f);
            if (n < NN) v = *(const float4*)&xin[(size_t)n * FIN + k4];
            *(float4*)&in_s[nl * FIN + k4] = v;
        }
        __syncthreads();

        unsigned long long acc[4][P];
        #pragma unroll
        for (int e = 0; e < 4; e++)
            #pragma unroll
            for (int p = 0; p < P; p++) acc[e][p] = 0ull;

        const unsigned long long* Ws2 = (const unsigned long long*)Ws_s;
        const float* in0 = &in_s[(w * 4) * FIN];

        for (int k4 = 0; k4 < FIN; k4 += 4) {
            float4 vv[4];
            #pragma unroll
            for (int e = 0; e < 4; e++)
                vv[e] = *(const float4*)&in0[e * FIN + k4];
            #pragma unroll
            for (int kk = 0; kk < 4; kk++) {
                const int k = k4 + kk;
                unsigned long long dup[4];
                #pragma unroll
                for (int e = 0; e < 4; e++) {
                    float v = (kk == 0) ? vv[e].x : (kk == 1) ? vv[e].y
                             : (kk == 2) ? vv[e].z : vv[e].w;
                    DUP2(dup[e], v);
                }
                #pragma unroll
                for (int p = 0; p < P; p++) {
                    unsigned long long w2 = Ws2[k * (F / 2) + p * 32 + lane];
                    #pragma unroll
                    for (int e = 0; e < 4; e++) FMA2(acc[e][p], dup[e], w2, acc[e][p]);
                }
            }
        }

        #pragma unroll
        for (int e = 0; e < 4; e++) {
            int n = base + w * 4 + e;
            if (n >= NN) continue;
            float inv = 1.0f / fmaxf(deg[n], 1.0f);
            const float* arow = agg + (size_t)n * F;
            float* frow = fout + (size_t)n * F;
            float cpart = 0.0f;
            #pragma unroll
            for (int p = 0; p < P; p++) {
                int c0 = p * 64 + lane * 2;
                float2 av = *(const float2*)&arow[c0];
                float lo = fmaxf(av.x * inv + __uint_as_float((unsigned)acc[e][p]) + bsr[p][0], 0.0f);
                float hi = fmaxf(av.y * inv + __uint_as_float((unsigned)(acc[e][p] >> 32)) + bsr[p][1], 0.0f);
                float2 ov; ov.x = lo; ov.y = hi;
                *(float2*)&frow[c0] = ov;
                cpart += lo * Wc_s[c0] + hi * Wc_s[c0 + 1];
            }
            #pragma unroll
            for (int off = 16; off; off >>= 1)
                cpart += __shfl_xor_sync(0xFFFFFFFFu, cpart, off);
            if (lane == 0) {
                int gg = gid[n];
                atomicAdd(&score[gg], (cpart + bcv) / fmaxf(gcnt[gg], 1.0f));
            }
        }
    }
}

// ---------------- host side ----------------
template <typename Kern>
static int grid_for(Kern k, int smem_bytes, int tiles, int nsm, int block) {
    cudaFuncSetAttribute(k, cudaFuncAttributeMaxDynamicSharedMemorySize, smem_bytes);
    int occ = 1;
    cudaOccupancyMaxActiveBlocksPerMultiprocessor(&occ, k, block, smem_bytes);
    if (occ < 1) occ = 1;
    int g = nsm * occ;
    if (g > tiles) g = tiles;
    return g;
}

template <int FIN, int F, int FK, int TILE>
static void launch_u(const float* xin, const float* Wm, float* u, int col_off, int nsm)
{
    constexpr int KP = FIN + 4;
    const int smem = FIN * FK * 4 + TILE * KP * 4;
    int g = grid_for(u_kernel<FIN, F, FK, TILE>, smem, (NN + TILE - 1) / TILE, nsm, 256);
    u_kernel<FIN, F, FK, TILE><<<g, 256, smem>>>(xin, Wm, u, col_off);
}

template <int F, int FK>
static void launch_edge(const float* u, const float* efeat, const int* src, const int* dst,
                        const float* Wme, const float* bm, float* agg, int col_off, int nsm)
{
    const int smem = EFD * FK * 4 + 128 * (EFD + 4) * 4 + 128 * (FK + 8) * 4 + 2 * 128 * 4;
    int g = grid_for(edge_mma_kernel<F, FK>, smem, EE / 128, nsm, 256);
    edge_mma_kernel<F, FK><<<g, 256, smem>>>(u, efeat, src, dst, Wme, bm, agg, col_off);
}

template <int FIN, int F>
static void launch_node(const float* xin, const float* agg, const float* const* Wl,
                        const int* gid, const float* deg, const float* gcnt,
                        float* fout, float* score, int nsm)
{
    const int smem_n = (FIN * F + F + 32 * FIN) * 4;
    int gn = grid_for(node_kernel<FIN, F>, smem_n, (NN + 31) / 32, nsm, 256);
    node_kernel<FIN, F><<<gn, 256, smem_n>>>(xin, agg, Wl[2], Wl[3], Wl[4], Wl[5],
                                             gid, deg, gcnt, fout, score);
}

extern "C" void kernel_launch(void* const* d_in, const int* in_sizes, int n_in,
                              void* d_out, int out_size)
{
    const float* x   = (const float*)d_in[0];
    const float* e   = (const float*)d_in[1];
    const int*   src = (const int*)d_in[2];
    const int*   dst = (const int*)d_in[3];
    const int*   gid = (const int*)d_in[4];
    const float* W[4][6];
    for (int l = 0; l < 4; l++)
        for (int j = 0; j < 6; j++)
            W[l][j] = (const float*)d_in[5 + l * 6 + j];
    float* score = (float*)d_out;

    float *bufA, *bufB, *agg, *uu, *deg, *gcnt;
    cudaGetSymbolAddress((void**)&bufA, g_bufA);
    cudaGetSymbolAddress((void**)&bufB, g_bufB);
    cudaGetSymbolAddress((void**)&agg, g_agg);
    cudaGetSymbolAddress((void**)&uu, g_u);
    cudaGetSymbolAddress((void**)&deg, g_deg);
    cudaGetSymbolAddress((void**)&gcnt, g_gcnt);

    int nsm = 148;
    cudaDeviceGetAttribute(&nsm, cudaDevAttrMultiProcessorCount, 0);

    cudaMemsetAsync(deg, 0, NN * sizeof(float));
    cudaMemsetAsync(gcnt, 0, GG * sizeof(float));
    cudaMemsetAsync(score, 0, GG * sizeof(float));
    count_kernel<<<(EE + 255) / 256, 256>>>(dst, gid, deg, gcnt);

    // layer 0: FIN=32, F=64
    cudaMemsetAsync(agg, 0, (size_t)NN * 64 * sizeof(float));
    launch_u<32, 64, 64, 128>(x, W[0][0], uu, 0, nsm);
    launch_edge<64, 64>(uu, e, src, dst, W[0][0] + 32 * 64, W[0][1], agg, 0, nsm);
    launch_node<32, 64>(x, agg, W[0], gid, deg, gcnt, bufA, score, nsm);

    // layer 1: FIN=64, F=128
    cudaMemsetAsync(agg, 0, (size_t)NN * 128 * sizeof(float));
    launch_u<64, 128, 128, 128>(bufA, W[1][0], uu, 0, nsm);
    launch_edge<128, 128>(uu, e, src, dst, W[1][0] + 64 * 128, W[1][1], agg, 0, nsm);
    launch_node<64, 128>(bufA, agg, W[1], gid, deg, gcnt, bufB, score, nsm);

    // layer 2: FIN=128, F=128
    cudaMemsetAsync(agg, 0, (size_t)NN * 128 * sizeof(float));
    launch_u<128, 128, 128, 64>(bufB, W[2][0], uu, 0, nsm);
    launch_edge<128, 128>(uu, e, src, dst, W[2][0] + 128 * 128, W[2][1], agg, 0, nsm);
    launch_node<128, 128>(bufB, agg, W[2], gid, deg, gcnt, bufA, score, nsm);

    // layer 3: FIN=128, F=256 (two FK=128 halves)
    cudaMemsetAsync(agg, 0, (size_t)NN * 256 * sizeof(float));
    launch_u<128, 256, 128, 64>(bufA, W[3][0], uu, 0, nsm);
    launch_u<128, 256, 128, 64>(bufA, W[3][0], uu, 128, nsm);
    launch_edge<256, 128>(uu, e, src, dst, W[3][0] + 128 * 256, W[3][1], agg, 0, nsm);
    launch_edge<256, 128>(uu, e, src, dst, W[3][0] + 128 * 256, W[3][1], agg, 128, nsm);
    launch_node<128, 256>(bufA, agg, W[3], gid, deg, gcnt, bufB, score, nsm);
}

// round 10
// speedup vs baseline: 3.1070x; 1.1543x over previous
#include <cuda_runtime.h>
#include <cuda_fp16.h>
#include <cstdint>

#define NN 50000
#define EE 800000
#define GG 512
#define EFD 16

// ---------------- scratch (no allocations allowed) ----------------
__device__ float g_bufA[NN * 256];
__device__ float g_bufB[NN * 256];
__device__ float g_agg[NN * 256];
__device__ __half g_uh[NN * 256];
__device__ float g_deg[NN];
__device__ float g_gcnt[GG];

// ---------------- helpers ----------------
__device__ __forceinline__ uint32_t f2tf32(float x) {
    uint32_t r;
    asm("cvt.rna.tf32.f32 %0, %1;" : "=r"(r) : "f"(x));
    return r;
}
__device__ __forceinline__ uint32_t smem_u32(const void* p) {
    uint32_t a;
    asm("{ .reg .u64 t; cvta.to.shared.u64 t, %1; cvt.u32.u64 %0, t; }" : "=r"(a) : "l"(p));
    return a;
}
__device__ __forceinline__ void cp16(uint32_t saddr, const void* gaddr) {
    asm volatile("cp.async.ca.shared.global [%0], [%1], 16;" :: "r"(saddr), "l"(gaddr) : "memory");
}
#define CP_COMMIT() asm volatile("cp.async.commit_group;" ::: "memory")
#define CP_WAIT(n)  asm volatile("cp.async.wait_group %0;" :: "n"(n) : "memory")

// D += A(16x8,row) * B(8x8,col), tf32 inputs, f32 accum
__device__ __forceinline__ void mma_tf32(float* d, const uint32_t* a, const uint32_t* b) {
    asm volatile(
        "mma.sync.aligned.m16n8k8.row.col.f32.tf32.tf32.f32 "
        "{%0,%1,%2,%3}, {%4,%5,%6,%7}, {%8,%9}, {%0,%1,%2,%3};"
        : "+f"(d[0]), "+f"(d[1]), "+f"(d[2]), "+f"(d[3])
        : "r"(a[0]), "r"(a[1]), "r"(a[2]), "r"(a[3]), "r"(b[0]), "r"(b[1]));
}

#define FMA2(d, a, b, c) \
    asm("fma.rn.f32x2 %0, %1, %2, %3;" : "=l"(d) : "l"(a), "l"(b), "l"(c))
#define DUP2(d, s) \
    asm("mov.b64 %0, {%1, %1};" : "=l"(d) : "r"(__float_as_uint(s)))

__global__ void count_kernel(const int* __restrict__ dst, const int* __restrict__ gid,
                             float* __restrict__ deg, float* __restrict__ gcnt) {
    int i = blockIdx.x * blockDim.x + threadIdx.x;
    if (i < EE) atomicAdd(&deg[dst[i]], 1.0f);
    if (i < NN) atomicAdd(&gcnt[gid[i]], 1.0f);
}

// ---------------- dense u-kernel: u[:, col_off:+FK] = feat @ Wm[0:FIN, col_off:+FK] (fp16 out) ----------------
template <int FIN, int F, int FK, int TILE>
__global__ __launch_bounds__(256)
void u_kernel(const float* __restrict__ xin, const float* __restrict__ Wm,
              __half2* __restrict__ uout, int col_off)
{
    constexpr int KP = FIN + 4;
    constexpr int KC8 = FIN / 8;
    constexpr int NT = FK / 16;
    constexpr int MI = TILE / 64;
    constexpr int TPR = 256 / TILE;
    constexpr int W_U32 = FIN * FK;

    extern __shared__ char smem[];
    uint32_t* Wp = (uint32_t*)smem;
    float* Abuf = (float*)(smem + (size_t)W_U32 * 4);

    const int tid = threadIdx.x;
    const int w = tid >> 5, lane = tid & 31;
    const int wm = w >> 1, wn = w & 1;
    const int g = lane >> 2, tg = lane & 3;
    const int row = tid / TPR, h = tid % TPR;
    const uint32_t sbA = smem_u32(Abuf);

    for (int i = tid; i < FIN * FK; i += 256) {
        int k = i / FK, n = i % FK;
        uint32_t val = f2tf32(Wm[k * F + col_off + n]);
        int T = n >> 3, kc = k >> 3;
        Wp[((T * KC8 + kc) * 32 + (n & 7) * 4 + (k & 3)) * 2 + ((k >> 2) & 1)] = val;
    }

    const int nTiles = (NN + TILE - 1) / TILE;
    const int stride = gridDim.x;

    auto gather = [&](int tile) {
        int grow = tile * TILE + row;
        if (grow >= NN) grow = NN - 1;
        uint32_t arow = sbA + (uint32_t)(row * KP) * 4;
        const char* xr = (const char*)(xin + (size_t)grow * FIN);
        #pragma unroll
        for (int c = h; c < FIN / 4; c += TPR) cp16(arow + c * 16, xr + c * 16);
    };

    int t0 = blockIdx.x;
    gather(t0);
    CP_COMMIT();

    for (int tile = t0; tile < nTiles; tile += stride) {
        CP_WAIT(0);
        __syncthreads();

        float acc[MI][NT][4];
        #pragma unroll
        for (int mi = 0; mi < MI; mi++)
            #pragma unroll
            for (int t = 0; t < NT; t++)
                #pragma unroll
                for (int j = 0; j < 4; j++) acc[mi][t][j] = 0.0f;

        for (int kc = 0; kc < KC8; kc++) {
            uint2 b[NT];
            #pragma unroll
            for (int t = 0; t < NT; t++)
                b[t] = *(const uint2*)&Wp[(((wn * NT + t) * KC8 + kc) * 32 + lane) * 2];
            #pragma unroll
            for (int mi = 0; mi < MI; mi++) {
                const float* ar = Abuf + (wm * (TILE / 4) + mi * 16 + g) * KP + kc * 8 + tg;
                uint32_t a[4];
                a[0] = f2tf32(ar[0]);
                a[1] = f2tf32(ar[8 * KP]);
                a[2] = f2tf32(ar[4]);
                a[3] = f2tf32(ar[8 * KP + 4]);
                #pragma unroll
                for (int t = 0; t < NT; t++)
                    mma_tf32(acc[mi][t], a, (const uint32_t*)&b[t]);
            }
        }
        __syncthreads();

        int nxt = tile + stride;
        if (nxt < nTiles) { gather(nxt); CP_COMMIT(); }

        const int base = tile * TILE;
        #pragma unroll
        for (int mi = 0; mi < MI; mi++) {
            int r0 = wm * (TILE / 4) + mi * 16 + g;
            int gr0 = base + r0, gr1 = gr0 + 8;
            #pragma unroll
            for (int t = 0; t < NT; t++) {
                int n = wn * (FK / 2) + t * 8 + tg * 2;
                if (gr0 < NN)
                    uout[(size_t)gr0 * (F / 2) + (col_off + n) / 2] =
                        __floats2half2_rn(acc[mi][t][0], acc[mi][t][1]);
                if (gr1 < NN)
                    uout[(size_t)gr1 * (F / 2) + (col_off + n) / 2] =
                        __floats2half2_rn(acc[mi][t][2], acc[mi][t][3]);
            }
        }
    }
}

// ---------------- edge kernel: agg[dst] += relu(u[src] + e @ Wme + bm), full F width ----------------
// 8 warps: 2 row-slabs (wm) x 4 col-groups (wn). TILE=128 (F<=128) or 64 (F=256).
template <int F, int TILE>
__global__ __launch_bounds__(256, 2)
void edge_mma_kernel(const __half2* __restrict__ u, const float* __restrict__ efeat,
                     const int* __restrict__ src, const int* __restrict__ dst,
                     const float* __restrict__ Wme,  // 16 rows, stride F
                     const float* __restrict__ bm,
                     float* __restrict__ agg)
{
    constexpr int K = EFD;               // 16
    constexpr int KP = K + 4;            // 20
    constexpr int KC8 = 2;
    constexpr int NT = F / 32;           // n8 tiles per warp (col group = F/4)
    constexpr int MI = TILE / 32;        // m16 tiles per row slab (slab = TILE/2)
    constexpr int TPR = 256 / TILE;
    constexpr int UW = F / 2 + 4;        // Ubuf stride in half2 words (16B-aligned rows, conflict-free)
    constexpr int W_U32 = K * F;
    constexpr int A_F32 = TILE * KP;
    constexpr int U_W32 = TILE * UW;

    extern __shared__ char smem[];
    uint32_t* Wp = (uint32_t*)smem;                                   // W_U32
    float* Abuf = (float*)(smem + (size_t)W_U32 * 4);                 // A_F32
    uint32_t* Ubuf = (uint32_t*)(Abuf + A_F32);                       // U_W32 (half2)
    int* sdst = (int*)(Ubuf + U_W32);                                 // 2*TILE

    const int tid = threadIdx.x;
    const int w = tid >> 5, lane = tid & 31;
    const int wm = w >> 2, wn = w & 3;
    const int g = lane >> 2, tg = lane & 3;
    const int row = tid / TPR, h = tid % TPR;
    const uint32_t sbA = smem_u32(Abuf);
    const uint32_t sbU = smem_u32(Ubuf);

    for (int i = tid; i < K * F; i += 256) {
        int k = i / F, n = i % F;
        uint32_t val = f2tf32(Wme[k * F + n]);
        int T = n >> 3, kc = k >> 3;
        Wp[((T * KC8 + kc) * 32 + (n & 7) * 4 + (k & 3)) * 2 + ((k >> 2) & 1)] = val;
    }
    float br[NT][2];
    #pragma unroll
    for (int t = 0; t < NT; t++) {
        int n = wn * (F / 4) + t * 8 + tg * 2;
        br[t][0] = bm[n];
        br[t][1] = bm[n + 1];
    }

    const int nTiles = EE / TILE;
    const int stride = gridDim.x;

    auto gather = [&](int tile, int par, int srow, int sd) {
        int base = tile * TILE;
        if (h == 0) sdst[par * TILE + row] = sd;
        uint32_t arow = sbA + (uint32_t)(row * KP) * 4;
        const char* er = (const char*)(efeat + (size_t)(base + row) * EFD);
        #pragma unroll
        for (int c = h; c < EFD / 4; c += TPR) cp16(arow + c * 16, er + c * 16);
        uint32_t urow = sbU + (uint32_t)(row * UW) * 4;
        const char* ur = (const char*)(u + (size_t)srow * (F / 2));
        #pragma unroll
        for (int c = h; c < F / 8; c += TPR) cp16(urow + c * 16, ur + c * 16);
    };

    int t0 = blockIdx.x;
    int ps = src[t0 * TILE + row];
    int pd = dst[t0 * TILE + row];
    gather(t0, 0, ps, pd);
    CP_COMMIT();
    int nxt0 = t0 + stride;
    if (nxt0 < nTiles) { ps = src[nxt0 * TILE + row]; pd = dst[nxt0 * TILE + row]; }

    int par = 0;
    for (int tile = t0; tile < nTiles; tile += stride) {
        CP_WAIT(0);
        __syncthreads();

        float acc[MI][NT][4];
        #pragma unroll
        for (int mi = 0; mi < MI; mi++)
            #pragma unroll
            for (int t = 0; t < NT; t++)
                #pragma unroll
                for (int j = 0; j < 4; j++) acc[mi][t][j] = 0.0f;

        #pragma unroll
        for (int kc = 0; kc < KC8; kc++) {
            uint2 b[NT];
            #pragma unroll
            for (int t = 0; t < NT; t++)
                b[t] = *(const uint2*)&Wp[(((wn * NT + t) * KC8 + kc) * 32 + lane) * 2];
            #pragma unroll
            for (int mi = 0; mi < MI; mi++) {
                const float* ar = Abuf + (wm * (TILE / 2) + mi * 16 + g) * KP + kc * 8 + tg;
                uint32_t a[4];
                a[0] = f2tf32(ar[0]);
                a[1] = f2tf32(ar[8 * KP]);
                a[2] = f2tf32(ar[4]);
                a[3] = f2tf32(ar[8 * KP + 4]);
                #pragma unroll
                for (int t = 0; t < NT; t++)
                    mma_tf32(acc[mi][t], a, (const uint32_t*)&b[t]);
            }
        }

        // add u + bias into acc (reads Ubuf), record dsts, then release buffers
        int d0[MI], d1[MI];
        #pragma unroll
        for (int mi = 0; mi < MI; mi++) {
            int r0 = wm * (TILE / 2) + mi * 16 + g;
            d0[mi] = sdst[par * TILE + r0];
            d1[mi] = sdst[par * TILE + r0 + 8];
            #pragma unroll
            for (int t = 0; t < NT; t++) {
                int hw = wn * (F / 8) + t * 4 + tg;   // half2 index
                __half2 u0 = *(const __half2*)&Ubuf[(size_t)r0 * UW + hw];
                __half2 u1 = *(const __half2*)&Ubuf[(size_t)(r0 + 8) * UW + hw];
                acc[mi][t][0] += __low2float(u0) + br[t][0];
                acc[mi][t][1] += __high2float(u0) + br[t][1];
                acc[mi][t][2] += __low2float(u1) + br[t][0];
                acc[mi][t][3] += __high2float(u1) + br[t][1];
            }
        }
        __syncthreads();   // all reads of Abuf/Ubuf/sdst done

        int nxt = tile + stride;
        if (nxt < nTiles) {
            gather(nxt, par ^ 1, ps, pd);
            CP_COMMIT();
            int nn2 = nxt + stride;
            if (nn2 < nTiles) { ps = src[nn2 * TILE + row]; pd = dst[nn2 * TILE + row]; }
        }

        // relu + atomic scatter (zero-skip), overlaps the in-flight cp.async
        #pragma unroll
        for (int mi = 0; mi < MI; mi++) {
            float* row0 = agg + (size_t)d0[mi] * F;
            float* row1 = agg + (size_t)d1[mi] * F;
            #pragma unroll
            for (int t = 0; t < NT; t++) {
                int n = wn * (F / 4) + t * 8 + tg * 2;
                if (acc[mi][t][0] > 0.0f) atomicAdd(&row0[n], acc[mi][t][0]);
                if (acc[mi][t][1] > 0.0f) atomicAdd(&row0[n + 1], acc[mi][t][1]);
                if (acc[mi][t][2] > 0.0f) atomicAdd(&row1[n], acc[mi][t][2]);
                if (acc[mi][t][3] > 0.0f) atomicAdd(&row1[n + 1], acc[mi][t][3]);
            }
        }
        par ^= 1;
    }
}

// ---------------- node kernel (FFMA f32x2) ----------------
template <int FIN, int F>
__global__ __launch_bounds__(256) void node_kernel(
    const float* __restrict__ xin, const float* __restrict__ agg,
    const float* __restrict__ Ws, const float* __restrict__ bs,
    const float* __restrict__ Wc, const float* __restrict__ bc,
    const int* __restrict__ gid, const float* __restrict__ deg,
    const float* __restrict__ gcnt,
    float* __restrict__ fout, float* __restrict__ score)
{
    constexpr int P = F / 64;
    extern __shared__ float smemf[];
    float* Ws_s = smemf;
    float* Wc_s = Ws_s + FIN * F;
    float* in_s = Wc_s + F;

    const int tid = threadIdx.x;
    const int w = tid >> 5, lane = tid & 31;

    for (int i = tid; i < FIN * F; i += 256) Ws_s[i] = Ws[i];
    for (int i = tid; i < F; i += 256) Wc_s[i] = Wc[i];
    float bsr[P][2];
    #pragma unroll
    for (int p = 0; p < P; p++) {
        bsr[p][0] = bs[p * 64 + lane * 2];
        bsr[p][1] = bs[p * 64 + lane * 2 + 1];
    }
    const float bcv = bc[0];
    __syncthreads();

    const int nTiles = (NN + 31) / 32;
    for (int tile = blockIdx.x; tile < nTiles; tile += gridDim.x) {
        const int base = tile * 32;
        __syncthreads();
        for (int i = tid; i < 32 * (FIN / 4); i += 256) {
            int nl = i / (FIN / 4);
            int k4 = (i % (FIN / 4)) * 4;
            int n = base + nl;
            float4 v = make_float4(0.f, 0.f, 0.f, 0.f);
            if (n < NN) v = *(const float4*)&xin[(size_t)n * FIN + k4];
            *(float4*)&in_s[nl * FIN + k4] = v;
        }
        __syncthreads();

        unsigned long long acc[4][P];
        #pragma unroll
        for (int e = 0; e < 4; e++)
            #pragma unroll
            for (int p = 0; p < P; p++) acc[e][p] = 0ull;

        const unsigned long long* Ws2 = (const unsigned long long*)Ws_s;
        const float* in0 = &in_s[(w * 4) * FIN];

        for (int k4 = 0; k4 < FIN; k4 += 4) {
            float4 vv[4];
            #pragma unroll
            for (int e = 0; e < 4; e++)
                vv[e] = *(const float4*)&in0[e * FIN + k4];
            #pragma unroll
            for (int kk = 0; kk < 4; kk++) {
                const int k = k4 + kk;
                unsigned long long dup[4];
                #pragma unroll
                for (int e = 0; e < 4; e++) {
                    float v = (kk == 0) ? vv[e].x : (kk == 1) ? vv[e].y
                             : (kk == 2) ? vv[e].z : vv[e].w;
                    DUP2(dup[e], v);
                }
                #pragma unroll
                for (int p = 0; p < P; p++) {
                    unsigned long long w2 = Ws2[k * (F / 2) + p * 32 + lane];
                    #pragma unroll
                    for (int e = 0; e < 4; e++) FMA2(acc[e][p], dup[e], w2, acc[e][p]);
                }
            }
        }

        #pragma unroll
        for (int e = 0; e < 4; e++) {
            int n = base + w * 4 + e;
            if (n >= NN) continue;
            float inv = 1.0f / fmaxf(deg[n], 1.0f);
            const float* arow = agg + (size_t)n * F;
            float* frow = fout + (size_t)n * F;
            float cpart = 0.0f;
            #pragma unroll
            for (int p = 0; p < P; p++) {
                int c0 = p * 64 + lane * 2;
                float2 av = *(const float2*)&arow[c0];
                float lo = fmaxf(av.x * inv + __uint_as_float((unsigned)acc[e][p]) + bsr[p][0], 0.0f);
                float hi = fmaxf(av.y * inv + __uint_as_float((unsigned)(acc[e][p] >> 32)) + bsr[p][1], 0.0f);
                float2 ov; ov.x = lo; ov.y = hi;
                *(float2*)&frow[c0] = ov;
                cpart += lo * Wc_s[c0] + hi * Wc_s[c0 + 1];
            }
            #pragma unroll
            for (int off = 16; off; off >>= 1)
                cpart += __shfl_xor_sync(0xFFFFFFFFu, cpart, off);
            if (lane == 0) {
                int gg = gid[n];
                atomicAdd(&score[gg], (cpart + bcv) / fmaxf(gcnt[gg], 1.0f));
            }
        }
    }
}

// ---------------- host side ----------------
template <typename Kern>
static int grid_for(Kern k, int smem_bytes, int tiles, int nsm, int block) {
    cudaFuncSetAttribute(k, cudaFuncAttributeMaxDynamicSharedMemorySize, smem_bytes);
    int occ = 1;
    cudaOccupancyMaxActiveBlocksPerMultiprocessor(&occ, k, block, smem_bytes);
    if (occ < 1) occ = 1;
    int g = nsm * occ;
    if (g > tiles) g = tiles;
    return g;
}

template <int FIN, int F, int FK, int TILE>
static void launch_u(const float* xin, const float* Wm, __half2* u, int col_off, int nsm)
{
    constexpr int KP = FIN + 4;
    const int smem = FIN * FK * 4 + TILE * KP * 4;
    int g = grid_for(u_kernel<FIN, F, FK, TILE>, smem, (NN + TILE - 1) / TILE, nsm, 256);
    u_kernel<FIN, F, FK, TILE><<<g, 256, smem>>>(xin, Wm, u, col_off);
}

template <int F, int TILE>
static void launch_edge(const __half2* u, const float* efeat, const int* src, const int* dst,
                        const float* Wme, const float* bm, float* agg, int nsm)
{
    const int smem = EFD * F * 4 + TILE * (EFD + 4) * 4 + TILE * (F / 2 + 4) * 4 + 2 * TILE * 4;
    int g = grid_for(edge_mma_kernel<F, TILE>, smem, EE / TILE, nsm, 256);
    edge_mma_kernel<F, TILE><<<g, 256, smem>>>(u, efeat, src, dst, Wme, bm, agg);
}

template <int FIN, int F>
static void launch_node(const float* xin, const float* agg, const float* const* Wl,
                        const int* gid, const float* deg, const float* gcnt,
                        float* fout, float* score, int nsm)
{
    const int smem_n = (FIN * F + F + 32 * FIN) * 4;
    int gn = grid_for(node_kernel<FIN, F>, smem_n, (NN + 31) / 32, nsm, 256);
    node_kernel<FIN, F><<<gn, 256, smem_n>>>(xin, agg, Wl[2], Wl[3], Wl[4], Wl[5],
                                             gid, deg, gcnt, fout, score);
}

extern "C" void kernel_launch(void* const* d_in, const int* in_sizes, int n_in,
                              void* d_out, int out_size)
{
    const float* x   = (const float*)d_in[0];
    const float* e   = (const float*)d_in[1];
    const int*   src = (const int*)d_in[2];
    const int*   dst = (const int*)d_in[3];
    const int*   gid = (const int*)d_in[4];
    const float* W[4][6];
    for (int l = 0; l < 4; l++)
        for (int j = 0; j < 6; j++)
            W[l][j] = (const float*)d_in[5 + l * 6 + j];
    float* score = (float*)d_out;

    float *bufA, *bufB, *agg, *deg, *gcnt;
    __half2* uh;
    cudaGetSymbolAddress((void**)&bufA, g_bufA);
    cudaGetSymbolAddress((void**)&bufB, g_bufB);
    cudaGetSymbolAddress((void**)&agg, g_agg);
    cudaGetSymbolAddress((void**)&uh, g_uh);
    cudaGetSymbolAddress((void**)&deg, g_deg);
    cudaGetSymbolAddress((void**)&gcnt, g_gcnt);

    int nsm = 148;
    cudaDeviceGetAttribute(&nsm, cudaDevAttrMultiProcessorCount, 0);

    cudaMemsetAsync(deg, 0, NN * sizeof(float));
    cudaMemsetAsync(gcnt, 0, GG * sizeof(float));
    cudaMemsetAsync(score, 0, GG * sizeof(float));
    count_kernel<<<(EE + 255) / 256, 256>>>(dst, gid, deg, gcnt);

    // layer 0: FIN=32, F=64
    cudaMemsetAsync(agg, 0, (size_t)NN * 64 * sizeof(float));
    launch_u<32, 64, 64, 128>(x, W[0][0], uh, 0, nsm);
    launch_edge<64, 128>(uh, e, src, dst, W[0][0] + 32 * 64, W[0][1], agg, nsm);
    launch_node<32, 64>(x, agg, W[0], gid, deg, gcnt, bufA, score, nsm);

    // layer 1: FIN=64, F=128
    cudaMemsetAsync(agg, 0, (size_t)NN * 128 * sizeof(float));
    launch_u<64, 128, 128, 128>(bufA, W[1][0], uh, 0, nsm);
    launch_edge<128, 128>(uh, e, src, dst, W[1][0] + 64 * 128, W[1][1], agg, nsm);
    launch_node<64, 128>(bufA, agg, W[1], gid, deg, gcnt, bufB, score, nsm);

    // layer 2: FIN=128, F=128
    cudaMemsetAsync(agg, 0, (size_t)NN * 128 * sizeof(float));
    launch_u<128, 128, 128, 64>(bufB, W[2][0], uh, 0, nsm);
    launch_edge<128, 128>(uh, e, src, dst, W[2][0] + 128 * 128, W[2][1], agg, nsm);
    launch_node<128, 128>(bufB, agg, W[2], gid, deg, gcnt, bufA, score, nsm);

    // layer 3: FIN=128, F=256 — u in two halves, edge in ONE full-width pass
    cudaMemsetAsync(agg, 0, (size_t)NN * 256 * sizeof(float));
    launch_u<128, 256, 128, 64>(bufA, W[3][0], uh, 0, nsm);
    launch_u<128, 256, 128, 64>(bufA, W[3][0], uh, 128, nsm);
    launch_edge<256, 64>(uh, e, src, dst, W[3][0] + 128 * 256, W[3][1], agg, nsm);
    launch_node<128, 256>(bufA, agg, W[3], gid, deg, gcnt, bufB, score, nsm);
}